// round 13
// baseline (speedup 1.0000x reference)
#include <cuda_runtime.h>
#include <cuda_bf16.h>

#define NMAX 50000
#define EMAX 600000
#define NT2 (2 * NMAX)
#define ET2 (2 * EMAX)
#define DIM 128
#define HEADS 4
#define FH 32
#define NEG_SLOPE 0.2f

// ---------------- scratch (static device globals; no allocs) ----------------
__device__ float d_x[NT2 * DIM];
__device__ __nv_bfloat16 d_hb[NT2 * DIM];
__device__ float d_asrc[NT2 * HEADS];
__device__ float d_adst[NT2 * HEADS];
__device__ float d_gvec[2 * DIM];
__device__ float d_gsum[2];
__device__ float d_gmax[12];
__device__ uint4 d_wpack[3 * 16 * 16 * 32];
__device__ int d_deg[NT2];
__device__ int d_off[NT2 + 1];
__device__ int d_cur[NT2];
__device__ int d_csrc[ET2];
__device__ int d_bsum[128];

__device__ __forceinline__ float leaky(float x) { return x > 0.f ? x : NEG_SLOPE * x; }

__device__ __forceinline__ unsigned f2tf32(float x) {
    unsigned r;
    asm("cvt.rna.tf32.f32 %0, %1;" : "=r"(r) : "f"(x));
    return r;
}

__device__ __forceinline__ float2 bf2f(unsigned w) {
    return __bfloat1622float2(*(__nv_bfloat162*)&w);
}

__device__ __forceinline__ void mma_tf32(float* d, const unsigned* a, unsigned b0, unsigned b1) {
    asm volatile("mma.sync.aligned.m16n8k8.row.col.f32.tf32.tf32.f32 "
                 "{%0,%1,%2,%3}, {%4,%5,%6,%7}, {%8,%9}, {%0,%1,%2,%3};\n"
                 : "+f"(d[0]), "+f"(d[1]), "+f"(d[2]), "+f"(d[3])
                 : "r"(a[0]), "r"(a[1]), "r"(a[2]), "r"(a[3]), "r"(b0), "r"(b1));
}

__device__ __forceinline__ void atomicMaxF(float* addr, float v) {
    int old = __float_as_int(*addr);
    while (__int_as_float(old) < v) {
        int assumed = old;
        old = atomicCAS((int*)addr, assumed, __float_as_int(v));
        if (old == assumed) break;
    }
}

// -------- zero scratch + W pre-pack into mma-fragment order (merged) --------
__global__ void k_prep(const float* __restrict__ W, int nt) {
    int i = blockIdx.x * blockDim.x + threadIdx.x;
    if (i < nt) d_deg[i] = 0;
    if (i < 12) d_gmax[i] = -1e30f;
    if (i < 2 * DIM) d_gvec[i] = 0.f;
    if (i < 2) d_gsum[i] = 0.f;
    if (i < 3 * 16 * 16 * 32) {
        int lane = i & 31;
        int n8g = (i >> 5) & 15;
        int kg = (i >> 9) & 15;
        int l = i >> 13;
        int lr = lane >> 2, lq = lane & 3;
        int k0 = kg * 8 + lq, k1 = kg * 8 + lq + 4;
        int nn = n8g * 8 + lr;
        const float* Wl = W + l * DIM * DIM;
        float w0 = Wl[k0 * DIM + nn];
        float w1 = Wl[k1 * DIM + nn];
        unsigned bh0 = f2tf32(w0), bh1 = f2tf32(w1);
        unsigned bl0 = f2tf32(w0 - __uint_as_float(bh0));
        unsigned bl1 = f2tf32(w1 - __uint_as_float(bh1));
        d_wpack[i] = make_uint4(bh0, bh1, bl0, bl1);
    }
}

// ---------------- CSR build ----------------
__global__ void k_hist2(const int* __restrict__ ei1, const int* __restrict__ ei2,
                        int E, int n) {
    int i = blockIdx.x * blockDim.x + threadIdx.x;
    if (i < E) atomicAdd(&d_deg[ei1[E + i]], 1);
    else if (i < 2 * E) atomicAdd(&d_deg[ei2[i] + n], 1);
}

__global__ void k_blocksum(int nt) {
    __shared__ int ws[8];
    int base = blockIdx.x * 2048 + threadIdx.x * 8;
    int s = 0;
    #pragma unroll
    for (int k = 0; k < 8; k++) {
        int i = base + k;
        if (i < nt) s += d_deg[i];
    }
    #pragma unroll
    for (int d = 16; d; d >>= 1) s += __shfl_down_sync(0xFFFFFFFFu, s, d);
    if ((threadIdx.x & 31) == 0) ws[threadIdx.x >> 5] = s;
    __syncthreads();
    if (threadIdx.x == 0) {
        int t = 0;
        #pragma unroll
        for (int w = 0; w < 8; w++) t += ws[w];
        d_bsum[blockIdx.x] = t;
    }
}

__global__ void k_scanlocal(int nt) {
    __shared__ int wtot[8];
    __shared__ int wexc[8];
    __shared__ int s_pref;
    int tid = threadIdx.x, lane = tid & 31, wid = tid >> 5;
    if (tid < 32) {
        int a = 0;
        for (int i = tid; i < blockIdx.x; i += 32) a += d_bsum[i];
        #pragma unroll
        for (int d = 16; d; d >>= 1) a += __shfl_down_sync(0xFFFFFFFFu, a, d);
        if (tid == 0) s_pref = a;
    }
    int base = blockIdx.x * 2048 + tid * 8;
    int vals[8];
    int tsum = 0;
    #pragma unroll
    for (int k = 0; k < 8; k++) {
        int i = base + k;
        vals[k] = (i < nt) ? d_deg[i] : 0;
        tsum += vals[k];
    }
    int x = tsum;
    #pragma unroll
    for (int d = 1; d < 32; d <<= 1) {
        int y = __shfl_up_sync(0xFFFFFFFFu, x, d);
        if (lane >= d) x += y;
    }
    if (lane == 31) wtot[wid] = x;
    __syncthreads();
    if (tid == 0) {
        int acc = 0;
        #pragma unroll
        for (int w = 0; w < 8; w++) { wexc[w] = acc; acc += wtot[w]; }
    }
    __syncthreads();
    int running = s_pref + wexc[wid] + (x - tsum);
    #pragma unroll
    for (int k = 0; k < 8; k++) {
        int i = base + k;
        if (i < nt) {
            d_off[i] = running;
            d_cur[i] = running;
            running += vals[k];
            if (i == nt - 1) d_off[nt] = running;
        }
    }
}

__global__ void k_scatter2(const int* __restrict__ ei1, const int* __restrict__ ei2,
                           int E, int n) {
    int i = blockIdx.x * blockDim.x + threadIdx.x;
    if (i < E) {
        int p = atomicAdd(&d_cur[ei1[E + i]], 1);
        d_csrc[p] = ei1[i];
    } else if (i < 2 * E) {
        int j = i - E;
        int p = atomicAdd(&d_cur[ei2[E + j] + n], 1);
        d_csrc[p] = ei2[j] + n;
    }
}

// ---------------- GEMM: fragment-major A smem + packed W, 2xTF32 ----------------
// 64-row tile, 256 threads (8 warps). Loader gathers A fragments directly:
// task (k,g): lane holds {x[g16+lr][k8+lq], x[g16+lr+8][k8+lq], x[..][+4], x[..+8][+4]}
// as one uint4 -> hot loop is 2x LDS.128 + 4x LDG.128 + 8 MMA per k.
__global__ __launch_bounds__(256) void k_gemm(const float* __restrict__ att_s,
                                              const float* __restrict__ att_d,
                                              int layer, int nt, int n,
                                              const int* __restrict__ x1,
                                              const int* __restrict__ x2,
                                              const float* __restrict__ embed) {
    __shared__ uint4 xf[16 * 4 * 32];   // [k][g][lane], 32 KB, conflict-free
    int tid = threadIdx.x, warp = tid >> 5, lane = tid & 31;
    int lr = lane >> 2, lq = lane & 3;
    int n0 = blockIdx.x * 64;

    #pragma unroll
    for (int i = 0; i < 8; i++) {
        int task = warp * 8 + i;
        int k = task >> 2, g = task & 3;
        int node0 = n0 + g * 16 + lr;
        int node1 = node0 + 8;
        float a0 = 0.f, a1 = 0.f, a2 = 0.f, a3 = 0.f;
        if (node0 < nt) {
            const float* row = (layer == 0)
                ? embed + (size_t)((node0 < n) ? x1[node0] : x2[node0 - n]) * DIM
                : d_x + (size_t)node0 * DIM;
            a0 = row[k * 8 + lq];
            a2 = row[k * 8 + lq + 4];
        }
        if (node1 < nt) {
            const float* row = (layer == 0)
                ? embed + (size_t)((node1 < n) ? x1[node1] : x2[node1 - n]) * DIM
                : d_x + (size_t)node1 * DIM;
            a1 = row[k * 8 + lq];
            a3 = row[k * 8 + lq + 4];
        }
        xf[task * 32 + lane] = make_uint4(f2tf32(a0), f2tf32(a1), f2tf32(a2), f2tf32(a3));
    }
    __syncthreads();

    int wm = warp & 1, wn = warp >> 1;          // wn = head = 32-col quarter
    const uint4* wp = d_wpack + layer * 8192 + (wn * 4) * 32 + lane;
    float acc[2][4][4];
    #pragma unroll
    for (int a = 0; a < 2; a++)
        #pragma unroll
        for (int b = 0; b < 4; b++)
            #pragma unroll
            for (int c = 0; c < 4; c++) acc[a][b][c] = 0.f;

    #pragma unroll 4
    for (int k = 0; k < 16; k++) {
        uint4 f0 = xf[(k * 4 + wm * 2 + 0) * 32 + lane];
        uint4 f1 = xf[(k * 4 + wm * 2 + 1) * 32 + lane];
        unsigned ahi[2][4] = {{f0.x, f0.y, f0.z, f0.w}, {f1.x, f1.y, f1.z, f1.w}};
        const uint4* wk = wp + k * 512;
        #pragma unroll
        for (int n8 = 0; n8 < 4; n8++) {
            uint4 b = __ldg(&wk[n8 * 32]);
            #pragma unroll
            for (int mt = 0; mt < 2; mt++) {
                mma_tf32(acc[mt][n8], ahi[mt], b.x, b.y);
                mma_tf32(acc[mt][n8], ahi[mt], b.z, b.w);
            }
        }
    }

    // epilogue: store h (bf16), per-head alpha dots (head = wn), global max
    float hs[4], hd[4];
    #pragma unroll
    for (int i = 0; i < 4; i++) { hs[i] = 0.f; hd[i] = 0.f; }

    #pragma unroll
    for (int n8 = 0; n8 < 4; n8++) {
        int nb = wn * 32 + n8 * 8 + 2 * lq;
        float2 s2 = *(const float2*)&att_s[nb];
        float2 dd2 = *(const float2*)&att_d[nb];
        #pragma unroll
        for (int mt = 0; mt < 2; mt++) {
            #pragma unroll
            for (int rh = 0; rh < 2; rh++) {
                float c0 = acc[mt][n8][rh * 2], c1 = acc[mt][n8][rh * 2 + 1];
                int node = n0 + wm * 32 + mt * 16 + rh * 8 + lr;
                if (node < nt)
                    *(__nv_bfloat162*)&d_hb[(size_t)node * DIM + nb] =
                        __floats2bfloat162_rn(c0, c1);
                int ri = mt * 2 + rh;
                hs[ri] += c0 * s2.x + c1 * s2.y;
                hd[ri] += c0 * dd2.x + c1 * dd2.y;
            }
        }
    }

    float wmax = -1e30f;
    #pragma unroll
    for (int ri = 0; ri < 4; ri++) {
        float vs = hs[ri], vd = hd[ri];
        vs += __shfl_xor_sync(0xFFFFFFFFu, vs, 1);
        vs += __shfl_xor_sync(0xFFFFFFFFu, vs, 2);
        vd += __shfl_xor_sync(0xFFFFFFFFu, vd, 1);
        vd += __shfl_xor_sync(0xFFFFFFFFu, vd, 2);
        int mt = ri >> 1, rh = ri & 1;
        int node = n0 + wm * 32 + mt * 16 + rh * 8 + lr;
        if (lq == 0 && node < nt) {
            d_asrc[node * HEADS + wn] = vs;
            d_adst[node * HEADS + wn] = vd;
        }
        wmax = fmaxf(wmax, vs);
    }
    #pragma unroll
    for (int d = 16; d; d >>= 1) wmax = fmaxf(wmax, __shfl_xor_sync(0xFFFFFFFFu, wmax, d));
    if (lane == 0) atomicMaxF(&d_gmax[layer * 4 + wn], wmax);
}

// ------ single-pass attention, half-warp edge parallel ------
__global__ __launch_bounds__(256) void k_attn(const float* __restrict__ bias,
                                              int layer, int nt, int n,
                                              const float* __restrict__ gw,
                                              const float* __restrict__ gb,
                                              int last) {
    __shared__ float sgv[2 * DIM];
    __shared__ float sgs[2];
    int tid = threadIdx.x;
    if (last) {
        if (tid < 2 * DIM) sgv[tid] = 0.f;
        if (tid < 2) sgs[tid] = 0.f;
        __syncthreads();
    }
    int warp = (blockIdx.x * 256 + tid) >> 5;
    int lane = tid & 31;
    int hw = lane >> 4;
    int sl = lane & 15;
    int h3 = sl >> 2;
    int fb = sl * 8 + hw * 4;
    bool active = warp < nt;
    int nidx = warp;
    float4 ra = make_float4(0.f, 0.f, 0.f, 0.f);

    if (active) {
        int beg = d_off[nidx], end = d_off[nidx + 1];
        float ad_h = __ldg(&d_adst[nidx * HEADS + h3]);
        float m_h = leaky(__ldg(&d_gmax[layer * 4 + h3]) + ad_h);
        float as_h = __ldg(&d_asrc[nidx * HEADS + h3]);
        float exself = __expf(leaky(as_h + ad_h) - m_h);
        float eself = hw ? 0.f : exself;

        uint4 sr = ((const uint4*)(d_hb + (size_t)nidx * DIM))[sl];
        float2 f0 = bf2f(sr.x), f1 = bf2f(sr.y), f2 = bf2f(sr.z), f3 = bf2f(sr.w);
        float4 accA = make_float4(eself * f0.x, eself * f0.y, eself * f1.x, eself * f1.y);
        float4 accB = make_float4(eself * f2.x, eself * f2.y, eself * f3.x, eself * f3.y);
        float sum = eself;

        for (int p = beg; p < end; p += 2) {
            int idx = p + hw;
            float valid = (idx < end) ? 1.f : 0.f;
            int s = d_csrc[min(idx, end - 1)];
            float a = __ldg(&d_asrc[s * HEADS + h3]);
            float e = valid * __expf(leaky(a + ad_h) - m_h);
            sum += e;
            uint4 r = ((const uint4*)(d_hb + (size_t)s * DIM))[sl];
            float2 g0 = bf2f(r.x), g1 = bf2f(r.y), g2 = bf2f(r.z), g3 = bf2f(r.w);
            accA.x += e * g0.x; accA.y += e * g0.y; accA.z += e * g1.x; accA.w += e * g1.y;
            accB.x += e * g2.x; accB.y += e * g2.y; accB.z += e * g3.x; accB.w += e * g3.y;
        }

        sum += __shfl_xor_sync(0xFFFFFFFFu, sum, 16);
        accA.x += __shfl_xor_sync(0xFFFFFFFFu, accA.x, 16);
        accA.y += __shfl_xor_sync(0xFFFFFFFFu, accA.y, 16);
        accA.z += __shfl_xor_sync(0xFFFFFFFFu, accA.z, 16);
        accA.w += __shfl_xor_sync(0xFFFFFFFFu, accA.w, 16);
        accB.x += __shfl_xor_sync(0xFFFFFFFFu, accB.x, 16);
        accB.y += __shfl_xor_sync(0xFFFFFFFFu, accB.y, 16);
        accB.z += __shfl_xor_sync(0xFFFFFFFFu, accB.z, 16);
        accB.w += __shfl_xor_sync(0xFFFFFFFFu, accB.w, 16);

        float inv = 1.f / sum;
        float4 acc = hw ? accB : accA;
        float4 b = *(const float4*)&bias[fb];
        ra.x = fmaxf(acc.x * inv + b.x, 0.f);
        ra.y = fmaxf(acc.y * inv + b.y, 0.f);
        ra.z = fmaxf(acc.z * inv + b.z, 0.f);
        ra.w = fmaxf(acc.w * inv + b.w, 0.f);
    }

    if (!last) {
        if (active)
            *(float4*)&d_x[(size_t)nidx * DIM + fb] = ra;
        return;
    }

    if (active) {
        float4 wv = *(const float4*)&gw[fb];
        float t = ra.x * wv.x + ra.y * wv.y + ra.z * wv.z + ra.w * wv.w;
        #pragma unroll
        for (int d = 16; d; d >>= 1) t += __shfl_xor_sync(0xFFFFFFFFu, t, d);
        float sg = 1.f / (1.f + __expf(-(t + gb[0])));
        float gate = __expf(sg);
        int g = (nidx >= n) ? 1 : 0;
        float* base = sgv + g * DIM + fb;
        atomicAdd(base + 0, gate * ra.x);
        atomicAdd(base + 1, gate * ra.y);
        atomicAdd(base + 2, gate * ra.z);
        atomicAdd(base + 3, gate * ra.w);
        if (lane == 0) atomicAdd(&sgs[g], gate);
    }
    __syncthreads();
    if (tid < 2 && sgs[tid] != 0.f) atomicAdd(&d_gsum[tid], sgs[tid]);
    for (int t = tid; t < 2 * DIM; t += 256) {
        float v = sgv[t];
        if (v != 0.f) atomicAdd(&d_gvec[t], v);
    }
}

// ---------------- final MLP ----------------
__global__ void k_final(const float* __restrict__ fc1_w, const float* __restrict__ fc1_b,
                        const float* __restrict__ fc2_w, const float* __restrict__ fc2_b,
                        float* __restrict__ out) {
    __shared__ float red[4];
    int j = threadIdx.x;
    float inv1 = 1.f / d_gsum[0];
    float inv2 = 1.f / d_gsum[1];
    float acc = fc1_b[j];
    #pragma unroll 4
    for (int k = 0; k < DIM; k++)
        acc += d_gvec[k] * inv1 * fc1_w[k * DIM + j];
    #pragma unroll 4
    for (int k = 0; k < DIM; k++)
        acc += d_gvec[DIM + k] * inv2 * fc1_w[(DIM + k) * DIM + j];
    float v = fmaxf(acc, 0.f) * fc2_w[j];
    #pragma unroll
    for (int d = 16; d; d >>= 1) v += __shfl_down_sync(0xFFFFFFFFu, v, d);
    if ((j & 31) == 0) red[j >> 5] = v;
    __syncthreads();
    if (j == 0) out[0] = red[0] + red[1] + red[2] + red[3] + fc2_b[0];
}

// ---------------- orchestration ----------------
static cudaStream_t g_s2 = nullptr;
static cudaEvent_t g_evFork = nullptr, g_evJoin = nullptr;

extern "C" void kernel_launch(void* const* d_in, const int* in_sizes, int n_in,
                              void* d_out, int out_size) {
    (void)n_in; (void)out_size;
    const int*   x1    = (const int*)d_in[0];
    const int*   x2    = (const int*)d_in[1];
    const int*   ei1   = (const int*)d_in[2];
    const int*   ei2   = (const int*)d_in[3];
    const float* embed = (const float*)d_in[4];
    const float* W     = (const float*)d_in[5];
    const float* att_s = (const float*)d_in[6];
    const float* att_d = (const float*)d_in[7];
    const float* bias  = (const float*)d_in[8];
    const float* gw    = (const float*)d_in[9];
    const float* gb    = (const float*)d_in[10];
    const float* fc1w  = (const float*)d_in[11];
    const float* fc1b  = (const float*)d_in[12];
    const float* fc2w  = (const float*)d_in[13];
    const float* fc2b  = (const float*)d_in[14];

    int N = in_sizes[0];
    int E = in_sizes[2] / 2;
    int NT = 2 * N;
    int nb = (NT + 2047) / 2048;

    if (!g_s2) {
        cudaStreamCreateWithFlags(&g_s2, cudaStreamNonBlocking);
        cudaEventCreateWithFlags(&g_evFork, cudaEventDisableTiming);
        cudaEventCreateWithFlags(&g_evJoin, cudaEventDisableTiming);
    }

    k_prep<<<(NT + 255) / 256, 256>>>(W, NT);
    k_hist2<<<(2 * E + 255) / 256, 256>>>(ei1, ei2, E, N);
    k_blocksum<<<nb, 256>>>(NT);

    cudaEventRecord(g_evFork, 0);
    cudaStreamWaitEvent(g_s2, g_evFork, 0);

    // 4th submitted launch -> ncu profiles this
    k_gemm<<<(NT + 63) / 64, 256>>>(att_s, att_d, 0, NT, N, x1, x2, embed);

    k_scanlocal<<<nb, 256, 0, g_s2>>>(NT);
    k_scatter2<<<(2 * E + 255) / 256, 256, 0, g_s2>>>(ei1, ei2, E, N);
    cudaEventRecord(g_evJoin, g_s2);
    cudaStreamWaitEvent(0, g_evJoin, 0);

    k_attn<<<(NT * 32 + 255) / 256, 256>>>(bias, 0, NT, N, gw, gb, 0);
    for (int l = 1; l < 3; l++) {
        k_gemm<<<(NT + 63) / 64, 256>>>(att_s + l * HEADS * FH,
                                        att_d + l * HEADS * FH,
                                        l, NT, N, x1, x2, embed);
        k_attn<<<(NT * 32 + 255) / 256, 256>>>(bias + l * DIM, l, NT, N,
                                               gw, gb, (l == 2) ? 1 : 0);
    }

    k_final<<<1, 128>>>(fc1w, fc1b, fc2w, fc2b, (float*)d_out);
}

// round 14
// speedup vs baseline: 1.0310x; 1.0310x over previous
#include <cuda_runtime.h>
#include <cuda_bf16.h>

#define NMAX 50000
#define EMAX 600000
#define NT2 (2 * NMAX)
#define ET2 (2 * EMAX)
#define DIM 128
#define HEADS 4
#define FH 32
#define NEG_SLOPE 0.2f

// ---------------- scratch (static device globals; no allocs) ----------------
__device__ float d_x[NT2 * DIM];
__device__ __nv_bfloat16 d_hb[NT2 * DIM];
__device__ float d_asrc[NT2 * HEADS];
__device__ float d_adst[NT2 * HEADS];
__device__ float d_gvec[2 * DIM];
__device__ float d_gsum[2];
__device__ float d_gmax[12];
__device__ uint4 d_wpack[3 * 16 * 16 * 32];
__device__ int d_deg[NT2];
__device__ int d_off[NT2 + 1];
__device__ int d_cur[NT2];
__device__ int d_csrc[ET2];
__device__ int d_bsum[128];

__device__ __forceinline__ float leaky(float x) { return x > 0.f ? x : NEG_SLOPE * x; }

__device__ __forceinline__ unsigned f2tf32(float x) {
    unsigned r;
    asm("cvt.rna.tf32.f32 %0, %1;" : "=r"(r) : "f"(x));
    return r;
}

__device__ __forceinline__ float2 bf2f(unsigned w) {
    return __bfloat1622float2(*(__nv_bfloat162*)&w);
}

__device__ __forceinline__ void mma_tf32(float* d, const unsigned* a, unsigned b0, unsigned b1) {
    asm volatile("mma.sync.aligned.m16n8k8.row.col.f32.tf32.tf32.f32 "
                 "{%0,%1,%2,%3}, {%4,%5,%6,%7}, {%8,%9}, {%0,%1,%2,%3};\n"
                 : "+f"(d[0]), "+f"(d[1]), "+f"(d[2]), "+f"(d[3])
                 : "r"(a[0]), "r"(a[1]), "r"(a[2]), "r"(a[3]), "r"(b0), "r"(b1));
}

__device__ __forceinline__ void atomicMaxF(float* addr, float v) {
    int old = __float_as_int(*addr);
    while (__int_as_float(old) < v) {
        int assumed = old;
        old = atomicCAS((int*)addr, assumed, __float_as_int(v));
        if (old == assumed) break;
    }
}

// -------- zero scratch + W pre-pack into mma-fragment order (merged) --------
__global__ void k_prep(const float* __restrict__ W, int nt) {
    int i = blockIdx.x * blockDim.x + threadIdx.x;
    if (i < nt) d_deg[i] = 0;
    if (i < 12) d_gmax[i] = -1e30f;
    if (i < 2 * DIM) d_gvec[i] = 0.f;
    if (i < 2) d_gsum[i] = 0.f;
    if (i < 3 * 16 * 16 * 32) {
        int lane = i & 31;
        int n8g = (i >> 5) & 15;
        int kg = (i >> 9) & 15;
        int l = i >> 13;
        int lr = lane >> 2, lq = lane & 3;
        int k0 = kg * 8 + lq, k1 = kg * 8 + lq + 4;
        int nn = n8g * 8 + lr;
        const float* Wl = W + l * DIM * DIM;
        float w0 = Wl[k0 * DIM + nn];
        float w1 = Wl[k1 * DIM + nn];
        unsigned bh0 = f2tf32(w0), bh1 = f2tf32(w1);
        unsigned bl0 = f2tf32(w0 - __uint_as_float(bh0));
        unsigned bl1 = f2tf32(w1 - __uint_as_float(bh1));
        d_wpack[i] = make_uint4(bh0, bh1, bl0, bl1);
    }
}

// ---------------- CSR build ----------------
__global__ void k_hist2(const int* __restrict__ ei1, const int* __restrict__ ei2,
                        int E, int n) {
    int i = blockIdx.x * blockDim.x + threadIdx.x;
    if (i < E) atomicAdd(&d_deg[ei1[E + i]], 1);
    else if (i < 2 * E) atomicAdd(&d_deg[ei2[i] + n], 1);
}

__global__ void k_blocksum(int nt) {
    __shared__ int ws[8];
    int base = blockIdx.x * 2048 + threadIdx.x * 8;
    int s = 0;
    #pragma unroll
    for (int k = 0; k < 8; k++) {
        int i = base + k;
        if (i < nt) s += d_deg[i];
    }
    #pragma unroll
    for (int d = 16; d; d >>= 1) s += __shfl_down_sync(0xFFFFFFFFu, s, d);
    if ((threadIdx.x & 31) == 0) ws[threadIdx.x >> 5] = s;
    __syncthreads();
    if (threadIdx.x == 0) {
        int t = 0;
        #pragma unroll
        for (int w = 0; w < 8; w++) t += ws[w];
        d_bsum[blockIdx.x] = t;
    }
}

__global__ void k_scanlocal(int nt) {
    __shared__ int wtot[8];
    __shared__ int wexc[8];
    __shared__ int s_pref;
    int tid = threadIdx.x, lane = tid & 31, wid = tid >> 5;
    if (tid < 32) {
        int a = 0;
        for (int i = tid; i < blockIdx.x; i += 32) a += d_bsum[i];
        #pragma unroll
        for (int d = 16; d; d >>= 1) a += __shfl_down_sync(0xFFFFFFFFu, a, d);
        if (tid == 0) s_pref = a;
    }
    int base = blockIdx.x * 2048 + tid * 8;
    int vals[8];
    int tsum = 0;
    #pragma unroll
    for (int k = 0; k < 8; k++) {
        int i = base + k;
        vals[k] = (i < nt) ? d_deg[i] : 0;
        tsum += vals[k];
    }
    int x = tsum;
    #pragma unroll
    for (int d = 1; d < 32; d <<= 1) {
        int y = __shfl_up_sync(0xFFFFFFFFu, x, d);
        if (lane >= d) x += y;
    }
    if (lane == 31) wtot[wid] = x;
    __syncthreads();
    if (tid == 0) {
        int acc = 0;
        #pragma unroll
        for (int w = 0; w < 8; w++) { wexc[w] = acc; acc += wtot[w]; }
    }
    __syncthreads();
    int running = s_pref + wexc[wid] + (x - tsum);
    #pragma unroll
    for (int k = 0; k < 8; k++) {
        int i = base + k;
        if (i < nt) {
            d_off[i] = running;
            d_cur[i] = running;
            running += vals[k];
            if (i == nt - 1) d_off[nt] = running;
        }
    }
}

__global__ void k_scatter2(const int* __restrict__ ei1, const int* __restrict__ ei2,
                           int E, int n) {
    int i = blockIdx.x * blockDim.x + threadIdx.x;
    if (i < E) {
        int p = atomicAdd(&d_cur[ei1[E + i]], 1);
        d_csrc[p] = ei1[i];
    } else if (i < 2 * E) {
        int j = i - E;
        int p = atomicAdd(&d_cur[ei2[E + j] + n], 1);
        d_csrc[p] = ei2[j] + n;
    }
}

// ------- GEMM: coalesced load -> smem repack to fragment-major -> 2xTF32 -------
// 64-row tile, 256 threads (8 warps). Stage 1: float4-coalesced x load, tf32'd
// into xs[64][132]. Stage 2: conflict-free repack into xf[k][g][lane] uint4.
// Hot loop: 2x LDS.128 + 4x LDG.128 + 8 MMA per k.
__global__ __launch_bounds__(256) void k_gemm(const float* __restrict__ att_s,
                                              const float* __restrict__ att_d,
                                              int layer, int nt, int n,
                                              const int* __restrict__ x1,
                                              const int* __restrict__ x2,
                                              const float* __restrict__ embed) {
    extern __shared__ unsigned smem_raw[];
    unsigned (*xs)[132] = (unsigned(*)[132])smem_raw;          // 33792 B
    uint4* xf = (uint4*)(smem_raw + 64 * 132);                  // 32768 B
    int tid = threadIdx.x, warp = tid >> 5, lane = tid & 31;
    int lr = lane >> 2, lq = lane & 3;
    int n0 = blockIdx.x * 64;

    // stage 1: coalesced load + tf32 convert
    for (int t = tid; t < 64 * 32; t += 256) {
        int r = t >> 5, c4 = t & 31;
        int node = n0 + r;
        float4 v = make_float4(0.f, 0.f, 0.f, 0.f);
        if (node < nt) {
            const float* row;
            if (layer == 0) {
                int id = (node < n) ? x1[node] : x2[node - n];
                row = embed + (size_t)id * DIM;
            } else {
                row = d_x + (size_t)node * DIM;
            }
            v = ((const float4*)row)[c4];
        }
        uint4 u = make_uint4(f2tf32(v.x), f2tf32(v.y), f2tf32(v.z), f2tf32(v.w));
        *(uint4*)&xs[r][c4 * 4] = u;
    }
    __syncthreads();

    // stage 2: repack to fragment-major (conflict-free scattered LDS)
    #pragma unroll
    for (int i = 0; i < 8; i++) {
        int task = warp * 8 + i;
        int k = task >> 2, g = task & 3;
        int row0 = g * 16 + lr, row1 = row0 + 8;
        unsigned a0 = xs[row0][k * 8 + lq];
        unsigned a1 = xs[row1][k * 8 + lq];
        unsigned a2 = xs[row0][k * 8 + lq + 4];
        unsigned a3 = xs[row1][k * 8 + lq + 4];
        xf[task * 32 + lane] = make_uint4(a0, a1, a2, a3);
    }
    __syncthreads();

    int wm = warp & 1, wn = warp >> 1;          // wn = head = 32-col quarter
    const uint4* wp = d_wpack + layer * 8192 + (wn * 4) * 32 + lane;
    float acc[2][4][4];
    #pragma unroll
    for (int a = 0; a < 2; a++)
        #pragma unroll
        for (int b = 0; b < 4; b++)
            #pragma unroll
            for (int c = 0; c < 4; c++) acc[a][b][c] = 0.f;

    #pragma unroll 4
    for (int k = 0; k < 16; k++) {
        uint4 f0 = xf[(k * 4 + wm * 2 + 0) * 32 + lane];
        uint4 f1 = xf[(k * 4 + wm * 2 + 1) * 32 + lane];
        unsigned ahi[2][4] = {{f0.x, f0.y, f0.z, f0.w}, {f1.x, f1.y, f1.z, f1.w}};
        const uint4* wk = wp + k * 512;
        #pragma unroll
        for (int n8 = 0; n8 < 4; n8++) {
            uint4 b = __ldg(&wk[n8 * 32]);
            #pragma unroll
            for (int mt = 0; mt < 2; mt++) {
                mma_tf32(acc[mt][n8], ahi[mt], b.x, b.y);
                mma_tf32(acc[mt][n8], ahi[mt], b.z, b.w);
            }
        }
    }

    // epilogue: store h (bf16), per-head alpha dots (head = wn), global max
    float hs[4], hd[4];
    #pragma unroll
    for (int i = 0; i < 4; i++) { hs[i] = 0.f; hd[i] = 0.f; }

    #pragma unroll
    for (int n8 = 0; n8 < 4; n8++) {
        int nb = wn * 32 + n8 * 8 + 2 * lq;
        float2 s2 = *(const float2*)&att_s[nb];
        float2 dd2 = *(const float2*)&att_d[nb];
        #pragma unroll
        for (int mt = 0; mt < 2; mt++) {
            #pragma unroll
            for (int rh = 0; rh < 2; rh++) {
                float c0 = acc[mt][n8][rh * 2], c1 = acc[mt][n8][rh * 2 + 1];
                int node = n0 + wm * 32 + mt * 16 + rh * 8 + lr;
                if (node < nt)
                    *(__nv_bfloat162*)&d_hb[(size_t)node * DIM + nb] =
                        __floats2bfloat162_rn(c0, c1);
                int ri = mt * 2 + rh;
                hs[ri] += c0 * s2.x + c1 * s2.y;
                hd[ri] += c0 * dd2.x + c1 * dd2.y;
            }
        }
    }

    float wmax = -1e30f;
    #pragma unroll
    for (int ri = 0; ri < 4; ri++) {
        float vs = hs[ri], vd = hd[ri];
        vs += __shfl_xor_sync(0xFFFFFFFFu, vs, 1);
        vs += __shfl_xor_sync(0xFFFFFFFFu, vs, 2);
        vd += __shfl_xor_sync(0xFFFFFFFFu, vd, 1);
        vd += __shfl_xor_sync(0xFFFFFFFFu, vd, 2);
        int mt = ri >> 1, rh = ri & 1;
        int node = n0 + wm * 32 + mt * 16 + rh * 8 + lr;
        if (lq == 0 && node < nt) {
            d_asrc[node * HEADS + wn] = vs;
            d_adst[node * HEADS + wn] = vd;
        }
        wmax = fmaxf(wmax, vs);
    }
    #pragma unroll
    for (int d = 16; d; d >>= 1) wmax = fmaxf(wmax, __shfl_xor_sync(0xFFFFFFFFu, wmax, d));
    if (lane == 0) atomicMaxF(&d_gmax[layer * 4 + wn], wmax);
}

// ------ single-pass attention, half-warp edge parallel ------
__global__ __launch_bounds__(256) void k_attn(const float* __restrict__ bias,
                                              int layer, int nt, int n,
                                              const float* __restrict__ gw,
                                              const float* __restrict__ gb,
                                              int last) {
    __shared__ float sgv[2 * DIM];
    __shared__ float sgs[2];
    int tid = threadIdx.x;
    if (last) {
        if (tid < 2 * DIM) sgv[tid] = 0.f;
        if (tid < 2) sgs[tid] = 0.f;
        __syncthreads();
    }
    int warp = (blockIdx.x * 256 + tid) >> 5;
    int lane = tid & 31;
    int hw = lane >> 4;
    int sl = lane & 15;
    int h3 = sl >> 2;
    int fb = sl * 8 + hw * 4;
    bool active = warp < nt;
    int nidx = warp;
    float4 ra = make_float4(0.f, 0.f, 0.f, 0.f);

    if (active) {
        int beg = d_off[nidx], end = d_off[nidx + 1];
        float ad_h = __ldg(&d_adst[nidx * HEADS + h3]);
        float m_h = leaky(__ldg(&d_gmax[layer * 4 + h3]) + ad_h);
        float as_h = __ldg(&d_asrc[nidx * HEADS + h3]);
        float exself = __expf(leaky(as_h + ad_h) - m_h);
        float eself = hw ? 0.f : exself;

        uint4 sr = ((const uint4*)(d_hb + (size_t)nidx * DIM))[sl];
        float2 f0 = bf2f(sr.x), f1 = bf2f(sr.y), f2 = bf2f(sr.z), f3 = bf2f(sr.w);
        float4 accA = make_float4(eself * f0.x, eself * f0.y, eself * f1.x, eself * f1.y);
        float4 accB = make_float4(eself * f2.x, eself * f2.y, eself * f3.x, eself * f3.y);
        float sum = eself;

        for (int p = beg; p < end; p += 2) {
            int idx = p + hw;
            float valid = (idx < end) ? 1.f : 0.f;
            int s = d_csrc[min(idx, end - 1)];
            float a = __ldg(&d_asrc[s * HEADS + h3]);
            float e = valid * __expf(leaky(a + ad_h) - m_h);
            sum += e;
            uint4 r = ((const uint4*)(d_hb + (size_t)s * DIM))[sl];
            float2 g0 = bf2f(r.x), g1 = bf2f(r.y), g2 = bf2f(r.z), g3 = bf2f(r.w);
            accA.x += e * g0.x; accA.y += e * g0.y; accA.z += e * g1.x; accA.w += e * g1.y;
            accB.x += e * g2.x; accB.y += e * g2.y; accB.z += e * g3.x; accB.w += e * g3.y;
        }

        sum += __shfl_xor_sync(0xFFFFFFFFu, sum, 16);
        accA.x += __shfl_xor_sync(0xFFFFFFFFu, accA.x, 16);
        accA.y += __shfl_xor_sync(0xFFFFFFFFu, accA.y, 16);
        accA.z += __shfl_xor_sync(0xFFFFFFFFu, accA.z, 16);
        accA.w += __shfl_xor_sync(0xFFFFFFFFu, accA.w, 16);
        accB.x += __shfl_xor_sync(0xFFFFFFFFu, accB.x, 16);
        accB.y += __shfl_xor_sync(0xFFFFFFFFu, accB.y, 16);
        accB.z += __shfl_xor_sync(0xFFFFFFFFu, accB.z, 16);
        accB.w += __shfl_xor_sync(0xFFFFFFFFu, accB.w, 16);

        float inv = 1.f / sum;
        float4 acc = hw ? accB : accA;
        float4 b = *(const float4*)&bias[fb];
        ra.x = fmaxf(acc.x * inv + b.x, 0.f);
        ra.y = fmaxf(acc.y * inv + b.y, 0.f);
        ra.z = fmaxf(acc.z * inv + b.z, 0.f);
        ra.w = fmaxf(acc.w * inv + b.w, 0.f);
    }

    if (!last) {
        if (active)
            *(float4*)&d_x[(size_t)nidx * DIM + fb] = ra;
        return;
    }

    if (active) {
        float4 wv = *(const float4*)&gw[fb];
        float t = ra.x * wv.x + ra.y * wv.y + ra.z * wv.z + ra.w * wv.w;
        #pragma unroll
        for (int d = 16; d; d >>= 1) t += __shfl_xor_sync(0xFFFFFFFFu, t, d);
        float sg = 1.f / (1.f + __expf(-(t + gb[0])));
        float gate = __expf(sg);
        int g = (nidx >= n) ? 1 : 0;
        float* base = sgv + g * DIM + fb;
        atomicAdd(base + 0, gate * ra.x);
        atomicAdd(base + 1, gate * ra.y);
        atomicAdd(base + 2, gate * ra.z);
        atomicAdd(base + 3, gate * ra.w);
        if (lane == 0) atomicAdd(&sgs[g], gate);
    }
    __syncthreads();
    if (tid < 2 && sgs[tid] != 0.f) atomicAdd(&d_gsum[tid], sgs[tid]);
    for (int t = tid; t < 2 * DIM; t += 256) {
        float v = sgv[t];
        if (v != 0.f) atomicAdd(&d_gvec[t], v);
    }
}

// ---------------- final MLP ----------------
__global__ void k_final(const float* __restrict__ fc1_w, const float* __restrict__ fc1_b,
                        const float* __restrict__ fc2_w, const float* __restrict__ fc2_b,
                        float* __restrict__ out) {
    __shared__ float red[4];
    int j = threadIdx.x;
    float inv1 = 1.f / d_gsum[0];
    float inv2 = 1.f / d_gsum[1];
    float acc = fc1_b[j];
    #pragma unroll 4
    for (int k = 0; k < DIM; k++)
        acc += d_gvec[k] * inv1 * fc1_w[k * DIM + j];
    #pragma unroll 4
    for (int k = 0; k < DIM; k++)
        acc += d_gvec[DIM + k] * inv2 * fc1_w[(DIM + k) * DIM + j];
    float v = fmaxf(acc, 0.f) * fc2_w[j];
    #pragma unroll
    for (int d = 16; d; d >>= 1) v += __shfl_down_sync(0xFFFFFFFFu, v, d);
    if ((j & 31) == 0) red[j >> 5] = v;
    __syncthreads();
    if (j == 0) out[0] = red[0] + red[1] + red[2] + red[3] + fc2_b[0];
}

// ---------------- orchestration ----------------
static cudaStream_t g_s2 = nullptr;
static cudaEvent_t g_evFork = nullptr, g_evJoin = nullptr;
#define GEMM_SMEM (64 * 132 * 4 + 16 * 4 * 32 * 16)

extern "C" void kernel_launch(void* const* d_in, const int* in_sizes, int n_in,
                              void* d_out, int out_size) {
    (void)n_in; (void)out_size;
    const int*   x1    = (const int*)d_in[0];
    const int*   x2    = (const int*)d_in[1];
    const int*   ei1   = (const int*)d_in[2];
    const int*   ei2   = (const int*)d_in[3];
    const float* embed = (const float*)d_in[4];
    const float* W     = (const float*)d_in[5];
    const float* att_s = (const float*)d_in[6];
    const float* att_d = (const float*)d_in[7];
    const float* bias  = (const float*)d_in[8];
    const float* gw    = (const float*)d_in[9];
    const float* gb    = (const float*)d_in[10];
    const float* fc1w  = (const float*)d_in[11];
    const float* fc1b  = (const float*)d_in[12];
    const float* fc2w  = (const float*)d_in[13];
    const float* fc2b  = (const float*)d_in[14];

    int N = in_sizes[0];
    int E = in_sizes[2] / 2;
    int NT = 2 * N;
    int nb = (NT + 2047) / 2048;

    if (!g_s2) {
        cudaStreamCreateWithFlags(&g_s2, cudaStreamNonBlocking);
        cudaEventCreateWithFlags(&g_evFork, cudaEventDisableTiming);
        cudaEventCreateWithFlags(&g_evJoin, cudaEventDisableTiming);
        cudaFuncSetAttribute(k_gemm, cudaFuncAttributeMaxDynamicSharedMemorySize, GEMM_SMEM);
    }

    k_prep<<<(NT + 255) / 256, 256>>>(W, NT);
    k_hist2<<<(2 * E + 255) / 256, 256>>>(ei1, ei2, E, N);
    k_blocksum<<<nb, 256>>>(NT);

    cudaEventRecord(g_evFork, 0);
    cudaStreamWaitEvent(g_s2, g_evFork, 0);

    // 4th submitted launch -> ncu profiles this
    k_gemm<<<(NT + 63) / 64, 256, GEMM_SMEM>>>(att_s, att_d, 0, NT, N, x1, x2, embed);

    k_scanlocal<<<nb, 256, 0, g_s2>>>(NT);
    k_scatter2<<<(2 * E + 255) / 256, 256, 0, g_s2>>>(ei1, ei2, E, N);
    cudaEventRecord(g_evJoin, g_s2);
    cudaStreamWaitEvent(0, g_evJoin, 0);

    k_attn<<<(NT * 32 + 255) / 256, 256>>>(bias, 0, NT, N, gw, gb, 0);
    for (int l = 1; l < 3; l++) {
        k_gemm<<<(NT + 63) / 64, 256, GEMM_SMEM>>>(att_s + l * HEADS * FH,
                                                   att_d + l * HEADS * FH,
                                                   l, NT, N, x1, x2, embed);
        k_attn<<<(NT * 32 + 255) / 256, 256>>>(bias + l * DIM, l, NT, N,
                                               gw, gb, (l == 2) ? 1 : 0);
    }

    k_final<<<1, 128>>>(fc1w, fc1b, fc2w, fc2b, (float*)d_out);
}

// round 15
// speedup vs baseline: 1.1183x; 1.0846x over previous
#include <cuda_runtime.h>
#include <cuda_bf16.h>

#define NMAX 50000
#define EMAX 600000
#define NT2 (2 * NMAX)
#define ET2 (2 * EMAX)
#define DIM 128
#define HEADS 4
#define FH 32
#define NEG_SLOPE 0.2f

// ---------------- scratch (static device globals; no allocs) ----------------
__device__ float d_x[NT2 * DIM];
__device__ __nv_bfloat16 d_hb[NT2 * DIM];
__device__ float d_asrc[NT2 * HEADS];
__device__ float d_adst[NT2 * HEADS];
__device__ float d_gvec[2 * DIM];
__device__ float d_gsum[2];
__device__ float d_gmax[12];
__device__ uint2 d_wpack2[3 * 16 * 16 * 32];  // [layer][kgroup][n8][lane] = bh0,bh1 (hi only)
__device__ int d_deg[NT2];
__device__ int d_off[NT2 + 1];
__device__ int d_cur[NT2];
__device__ int d_csrc[ET2];
__device__ int d_bsum[128];

__device__ __forceinline__ float leaky(float x) { return x > 0.f ? x : NEG_SLOPE * x; }

__device__ __forceinline__ unsigned f2tf32(float x) {
    unsigned r;
    asm("cvt.rna.tf32.f32 %0, %1;" : "=r"(r) : "f"(x));
    return r;
}

__device__ __forceinline__ float2 bf2f(unsigned w) {
    return __bfloat1622float2(*(__nv_bfloat162*)&w);
}

__device__ __forceinline__ void mma_tf32(float* d, const unsigned* a, unsigned b0, unsigned b1) {
    asm volatile("mma.sync.aligned.m16n8k8.row.col.f32.tf32.tf32.f32 "
                 "{%0,%1,%2,%3}, {%4,%5,%6,%7}, {%8,%9}, {%0,%1,%2,%3};\n"
                 : "+f"(d[0]), "+f"(d[1]), "+f"(d[2]), "+f"(d[3])
                 : "r"(a[0]), "r"(a[1]), "r"(a[2]), "r"(a[3]), "r"(b0), "r"(b1));
}

__device__ __forceinline__ void atomicMaxF(float* addr, float v) {
    int old = __float_as_int(*addr);
    while (__int_as_float(old) < v) {
        int assumed = old;
        old = atomicCAS((int*)addr, assumed, __float_as_int(v));
        if (old == assumed) break;
    }
}

// -------- zero scratch + W pre-pack (hi-only tf32, fragment order) --------
__global__ void k_prep(const float* __restrict__ W, int nt) {
    int i = blockIdx.x * blockDim.x + threadIdx.x;
    if (i < nt) d_deg[i] = 0;
    if (i < 12) d_gmax[i] = -1e30f;
    if (i < 2 * DIM) d_gvec[i] = 0.f;
    if (i < 2) d_gsum[i] = 0.f;
    if (i < 3 * 16 * 16 * 32) {
        int lane = i & 31;
        int n8g = (i >> 5) & 15;
        int kg = (i >> 9) & 15;
        int l = i >> 13;
        int lr = lane >> 2, lq = lane & 3;
        int k0 = kg * 8 + lq, k1 = kg * 8 + lq + 4;
        int nn = n8g * 8 + lr;
        const float* Wl = W + l * DIM * DIM;
        d_wpack2[i] = make_uint2(f2tf32(Wl[k0 * DIM + nn]), f2tf32(Wl[k1 * DIM + nn]));
    }
}

// ---------------- CSR build ----------------
__global__ void k_hist2(const int* __restrict__ ei1, const int* __restrict__ ei2,
                        int E, int n) {
    int i = blockIdx.x * blockDim.x + threadIdx.x;
    if (i < E) atomicAdd(&d_deg[ei1[E + i]], 1);
    else if (i < 2 * E) atomicAdd(&d_deg[ei2[i] + n], 1);
}

__global__ void k_blocksum(int nt) {
    __shared__ int ws[8];
    int base = blockIdx.x * 2048 + threadIdx.x * 8;
    int s = 0;
    #pragma unroll
    for (int k = 0; k < 8; k++) {
        int i = base + k;
        if (i < nt) s += d_deg[i];
    }
    #pragma unroll
    for (int d = 16; d; d >>= 1) s += __shfl_down_sync(0xFFFFFFFFu, s, d);
    if ((threadIdx.x & 31) == 0) ws[threadIdx.x >> 5] = s;
    __syncthreads();
    if (threadIdx.x == 0) {
        int t = 0;
        #pragma unroll
        for (int w = 0; w < 8; w++) t += ws[w];
        d_bsum[blockIdx.x] = t;
    }
}

__global__ void k_scanlocal(int nt) {
    __shared__ int wtot[8];
    __shared__ int wexc[8];
    __shared__ int s_pref;
    int tid = threadIdx.x, lane = tid & 31, wid = tid >> 5;
    if (tid < 32) {
        int a = 0;
        for (int i = tid; i < blockIdx.x; i += 32) a += d_bsum[i];
        #pragma unroll
        for (int d = 16; d; d >>= 1) a += __shfl_down_sync(0xFFFFFFFFu, a, d);
        if (tid == 0) s_pref = a;
    }
    int base = blockIdx.x * 2048 + tid * 8;
    int vals[8];
    int tsum = 0;
    #pragma unroll
    for (int k = 0; k < 8; k++) {
        int i = base + k;
        vals[k] = (i < nt) ? d_deg[i] : 0;
        tsum += vals[k];
    }
    int x = tsum;
    #pragma unroll
    for (int d = 1; d < 32; d <<= 1) {
        int y = __shfl_up_sync(0xFFFFFFFFu, x, d);
        if (lane >= d) x += y;
    }
    if (lane == 31) wtot[wid] = x;
    __syncthreads();
    if (tid == 0) {
        int acc = 0;
        #pragma unroll
        for (int w = 0; w < 8; w++) { wexc[w] = acc; acc += wtot[w]; }
    }
    __syncthreads();
    int running = s_pref + wexc[wid] + (x - tsum);
    #pragma unroll
    for (int k = 0; k < 8; k++) {
        int i = base + k;
        if (i < nt) {
            d_off[i] = running;
            d_cur[i] = running;
            running += vals[k];
            if (i == nt - 1) d_off[nt] = running;
        }
    }
}

__global__ void k_scatter2(const int* __restrict__ ei1, const int* __restrict__ ei2,
                           int E, int n) {
    int i = blockIdx.x * blockDim.x + threadIdx.x;
    if (i < E) {
        int p = atomicAdd(&d_cur[ei1[E + i]], 1);
        d_csrc[p] = ei1[i];
    } else if (i < 2 * E) {
        int j = i - E;
        int p = atomicAdd(&d_cur[ei2[E + j] + n], 1);
        d_csrc[p] = ei2[j] + n;
    }
}

// ---------------- GEMM: h = x @ W via single-tf32, hi-only packed W ----------------
// Round-12 structure: 64-row tile, 256 threads (8 warps), xs[64][132] tf32 smem.
// Hot loop per k: 8 LDS.32 (A) + 4 LDG.64 (W hi) + 8 MMA.
__global__ __launch_bounds__(256) void k_gemm(const float* __restrict__ att_s,
                                              const float* __restrict__ att_d,
                                              int layer, int nt, int n,
                                              const int* __restrict__ x1,
                                              const int* __restrict__ x2,
                                              const float* __restrict__ embed) {
    __shared__ unsigned xs[64][132];
    int tid = threadIdx.x, warp = tid >> 5, lane = tid & 31;
    int lr = lane >> 2, lq = lane & 3;
    int n0 = blockIdx.x * 64;

    for (int t = tid; t < 64 * 32; t += 256) {
        int r = t >> 5, c4 = t & 31;
        int node = n0 + r;
        float4 v = make_float4(0.f, 0.f, 0.f, 0.f);
        if (node < nt) {
            const float* row;
            if (layer == 0) {
                int id = (node < n) ? x1[node] : x2[node - n];
                row = embed + (size_t)id * DIM;
            } else {
                row = d_x + (size_t)node * DIM;
            }
            v = ((const float4*)row)[c4];
        }
        uint4 u = make_uint4(f2tf32(v.x), f2tf32(v.y), f2tf32(v.z), f2tf32(v.w));
        *(uint4*)&xs[r][c4 * 4] = u;
    }
    __syncthreads();

    int wm = warp & 1, wn = warp >> 1;          // wn = head = 32-col quarter
    const uint2* wp = d_wpack2 + layer * 8192 + (wn * 4) * 32 + lane;
    float acc[2][4][4];
    #pragma unroll
    for (int a = 0; a < 2; a++)
        #pragma unroll
        for (int b = 0; b < 4; b++)
            #pragma unroll
            for (int c = 0; c < 4; c++) acc[a][b][c] = 0.f;

    #pragma unroll 4
    for (int k = 0; k < 16; k++) {
        int kb = k * 8;
        unsigned ahi[2][4];
        #pragma unroll
        for (int mt = 0; mt < 2; mt++) {
            int rb = wm * 32 + mt * 16;
            ahi[mt][0] = xs[rb + lr][kb + lq];
            ahi[mt][1] = xs[rb + lr + 8][kb + lq];
            ahi[mt][2] = xs[rb + lr][kb + lq + 4];
            ahi[mt][3] = xs[rb + lr + 8][kb + lq + 4];
        }
        const uint2* wk = wp + k * 512;
        #pragma unroll
        for (int n8 = 0; n8 < 4; n8++) {
            uint2 b = __ldg(&wk[n8 * 32]);
            #pragma unroll
            for (int mt = 0; mt < 2; mt++) {
                mma_tf32(acc[mt][n8], ahi[mt], b.x, b.y);
            }
        }
    }

    // epilogue: store h (bf16), per-head alpha dots (head = wn), global max
    float hs[4], hd[4];
    #pragma unroll
    for (int i = 0; i < 4; i++) { hs[i] = 0.f; hd[i] = 0.f; }

    #pragma unroll
    for (int n8 = 0; n8 < 4; n8++) {
        int nb = wn * 32 + n8 * 8 + 2 * lq;
        float2 s2 = *(const float2*)&att_s[nb];
        float2 dd2 = *(const float2*)&att_d[nb];
        #pragma unroll
        for (int mt = 0; mt < 2; mt++) {
            #pragma unroll
            for (int rh = 0; rh < 2; rh++) {
                float c0 = acc[mt][n8][rh * 2], c1 = acc[mt][n8][rh * 2 + 1];
                int node = n0 + wm * 32 + mt * 16 + rh * 8 + lr;
                if (node < nt)
                    *(__nv_bfloat162*)&d_hb[(size_t)node * DIM + nb] =
                        __floats2bfloat162_rn(c0, c1);
                int ri = mt * 2 + rh;
                hs[ri] += c0 * s2.x + c1 * s2.y;
                hd[ri] += c0 * dd2.x + c1 * dd2.y;
            }
        }
    }

    float wmax = -1e30f;
    #pragma unroll
    for (int ri = 0; ri < 4; ri++) {
        float vs = hs[ri], vd = hd[ri];
        vs += __shfl_xor_sync(0xFFFFFFFFu, vs, 1);
        vs += __shfl_xor_sync(0xFFFFFFFFu, vs, 2);
        vd += __shfl_xor_sync(0xFFFFFFFFu, vd, 1);
        vd += __shfl_xor_sync(0xFFFFFFFFu, vd, 2);
        int mt = ri >> 1, rh = ri & 1;
        int node = n0 + wm * 32 + mt * 16 + rh * 8 + lr;
        if (lq == 0 && node < nt) {
            d_asrc[node * HEADS + wn] = vs;
            d_adst[node * HEADS + wn] = vd;
        }
        wmax = fmaxf(wmax, vs);
    }
    #pragma unroll
    for (int d = 16; d; d >>= 1) wmax = fmaxf(wmax, __shfl_xor_sync(0xFFFFFFFFu, wmax, d));
    if (lane == 0) atomicMaxF(&d_gmax[layer * 4 + wn], wmax);
}

// ------ single-pass attention, half-warp edge parallel ------
__global__ __launch_bounds__(256) void k_attn(const float* __restrict__ bias,
                                              int layer, int nt, int n,
                                              const float* __restrict__ gw,
                                              const float* __restrict__ gb,
                                              int last) {
    __shared__ float sgv[2 * DIM];
    __shared__ float sgs[2];
    int tid = threadIdx.x;
    if (last) {
        if (tid < 2 * DIM) sgv[tid] = 0.f;
        if (tid < 2) sgs[tid] = 0.f;
        __syncthreads();
    }
    int warp = (blockIdx.x * 256 + tid) >> 5;
    int lane = tid & 31;
    int hw = lane >> 4;
    int sl = lane & 15;
    int h3 = sl >> 2;
    int fb = sl * 8 + hw * 4;
    bool active = warp < nt;
    int nidx = warp;
    float4 ra = make_float4(0.f, 0.f, 0.f, 0.f);

    if (active) {
        int beg = d_off[nidx], end = d_off[nidx + 1];
        float ad_h = __ldg(&d_adst[nidx * HEADS + h3]);
        float m_h = leaky(__ldg(&d_gmax[layer * 4 + h3]) + ad_h);
        float as_h = __ldg(&d_asrc[nidx * HEADS + h3]);
        float exself = __expf(leaky(as_h + ad_h) - m_h);
        float eself = hw ? 0.f : exself;

        uint4 sr = ((const uint4*)(d_hb + (size_t)nidx * DIM))[sl];
        float2 f0 = bf2f(sr.x), f1 = bf2f(sr.y), f2 = bf2f(sr.z), f3 = bf2f(sr.w);
        float4 accA = make_float4(eself * f0.x, eself * f0.y, eself * f1.x, eself * f1.y);
        float4 accB = make_float4(eself * f2.x, eself * f2.y, eself * f3.x, eself * f3.y);
        float sum = eself;

        for (int p = beg; p < end; p += 2) {
            int idx = p + hw;
            float valid = (idx < end) ? 1.f : 0.f;
            int s = d_csrc[min(idx, end - 1)];
            float a = __ldg(&d_asrc[s * HEADS + h3]);
            float e = valid * __expf(leaky(a + ad_h) - m_h);
            sum += e;
            uint4 r = ((const uint4*)(d_hb + (size_t)s * DIM))[sl];
            float2 g0 = bf2f(r.x), g1 = bf2f(r.y), g2 = bf2f(r.z), g3 = bf2f(r.w);
            accA.x += e * g0.x; accA.y += e * g0.y; accA.z += e * g1.x; accA.w += e * g1.y;
            accB.x += e * g2.x; accB.y += e * g2.y; accB.z += e * g3.x; accB.w += e * g3.y;
        }

        sum += __shfl_xor_sync(0xFFFFFFFFu, sum, 16);
        accA.x += __shfl_xor_sync(0xFFFFFFFFu, accA.x, 16);
        accA.y += __shfl_xor_sync(0xFFFFFFFFu, accA.y, 16);
        accA.z += __shfl_xor_sync(0xFFFFFFFFu, accA.z, 16);
        accA.w += __shfl_xor_sync(0xFFFFFFFFu, accA.w, 16);
        accB.x += __shfl_xor_sync(0xFFFFFFFFu, accB.x, 16);
        accB.y += __shfl_xor_sync(0xFFFFFFFFu, accB.y, 16);
        accB.z += __shfl_xor_sync(0xFFFFFFFFu, accB.z, 16);
        accB.w += __shfl_xor_sync(0xFFFFFFFFu, accB.w, 16);

        float inv = 1.f / sum;
        float4 acc = hw ? accB : accA;
        float4 b = *(const float4*)&bias[fb];
        ra.x = fmaxf(acc.x * inv + b.x, 0.f);
        ra.y = fmaxf(acc.y * inv + b.y, 0.f);
        ra.z = fmaxf(acc.z * inv + b.z, 0.f);
        ra.w = fmaxf(acc.w * inv + b.w, 0.f);
    }

    if (!last) {
        if (active)
            *(float4*)&d_x[(size_t)nidx * DIM + fb] = ra;
        return;
    }

    if (active) {
        float4 wv = *(const float4*)&gw[fb];
        float t = ra.x * wv.x + ra.y * wv.y + ra.z * wv.z + ra.w * wv.w;
        #pragma unroll
        for (int d = 16; d; d >>= 1) t += __shfl_xor_sync(0xFFFFFFFFu, t, d);
        float sg = 1.f / (1.f + __expf(-(t + gb[0])));
        float gate = __expf(sg);
        int g = (nidx >= n) ? 1 : 0;
        float* base = sgv + g * DIM + fb;
        atomicAdd(base + 0, gate * ra.x);
        atomicAdd(base + 1, gate * ra.y);
        atomicAdd(base + 2, gate * ra.z);
        atomicAdd(base + 3, gate * ra.w);
        if (lane == 0) atomicAdd(&sgs[g], gate);
    }
    __syncthreads();
    if (tid < 2 && sgs[tid] != 0.f) atomicAdd(&d_gsum[tid], sgs[tid]);
    for (int t = tid; t < 2 * DIM; t += 256) {
        float v = sgv[t];
        if (v != 0.f) atomicAdd(&d_gvec[t], v);
    }
}

// ---------------- final MLP ----------------
__global__ void k_final(const float* __restrict__ fc1_w, const float* __restrict__ fc1_b,
                        const float* __restrict__ fc2_w, const float* __restrict__ fc2_b,
                        float* __restrict__ out) {
    __shared__ float red[4];
    int j = threadIdx.x;
    float inv1 = 1.f / d_gsum[0];
    float inv2 = 1.f / d_gsum[1];
    float acc = fc1_b[j];
    #pragma unroll 4
    for (int k = 0; k < DIM; k++)
        acc += d_gvec[k] * inv1 * fc1_w[k * DIM + j];
    #pragma unroll 4
    for (int k = 0; k < DIM; k++)
        acc += d_gvec[DIM + k] * inv2 * fc1_w[(DIM + k) * DIM + j];
    float v = fmaxf(acc, 0.f) * fc2_w[j];
    #pragma unroll
    for (int d = 16; d; d >>= 1) v += __shfl_down_sync(0xFFFFFFFFu, v, d);
    if ((j & 31) == 0) red[j >> 5] = v;
    __syncthreads();
    if (j == 0) out[0] = red[0] + red[1] + red[2] + red[3] + fc2_b[0];
}

// ---------------- orchestration ----------------
static cudaStream_t g_s2 = nullptr;
static cudaEvent_t g_evFork = nullptr, g_evJoin = nullptr;

extern "C" void kernel_launch(void* const* d_in, const int* in_sizes, int n_in,
                              void* d_out, int out_size) {
    (void)n_in; (void)out_size;
    const int*   x1    = (const int*)d_in[0];
    const int*   x2    = (const int*)d_in[1];
    const int*   ei1   = (const int*)d_in[2];
    const int*   ei2   = (const int*)d_in[3];
    const float* embed = (const float*)d_in[4];
    const float* W     = (const float*)d_in[5];
    const float* att_s = (const float*)d_in[6];
    const float* att_d = (const float*)d_in[7];
    const float* bias  = (const float*)d_in[8];
    const float* gw    = (const float*)d_in[9];
    const float* gb    = (const float*)d_in[10];
    const float* fc1w  = (const float*)d_in[11];
    const float* fc1b  = (const float*)d_in[12];
    const float* fc2w  = (const float*)d_in[13];
    const float* fc2b  = (const float*)d_in[14];

    int N = in_sizes[0];
    int E = in_sizes[2] / 2;
    int NT = 2 * N;
    int nb = (NT + 2047) / 2048;

    if (!g_s2) {
        cudaStreamCreateWithFlags(&g_s2, cudaStreamNonBlocking);
        cudaEventCreateWithFlags(&g_evFork, cudaEventDisableTiming);
        cudaEventCreateWithFlags(&g_evJoin, cudaEventDisableTiming);
    }

    k_prep<<<(NT + 255) / 256, 256>>>(W, NT);
    k_hist2<<<(2 * E + 255) / 256, 256>>>(ei1, ei2, E, N);
    k_blocksum<<<nb, 256>>>(NT);

    cudaEventRecord(g_evFork, 0);
    cudaStreamWaitEvent(g_s2, g_evFork, 0);

    // 4th submitted launch -> ncu profiles this
    k_gemm<<<(NT + 63) / 64, 256>>>(att_s, att_d, 0, NT, N, x1, x2, embed);

    k_scanlocal<<<nb, 256, 0, g_s2>>>(NT);
    k_scatter2<<<(2 * E + 255) / 256, 256, 0, g_s2>>>(ei1, ei2, E, N);
    cudaEventRecord(g_evJoin, g_s2);
    cudaStreamWaitEvent(0, g_evJoin, 0);

    k_attn<<<(NT * 32 + 255) / 256, 256>>>(bias, 0, NT, N, gw, gb, 0);
    for (int l = 1; l < 3; l++) {
        k_gemm<<<(NT + 63) / 64, 256>>>(att_s + l * HEADS * FH,
                                        att_d + l * HEADS * FH,
                                        l, NT, N, x1, x2, embed);
        k_attn<<<(NT * 32 + 255) / 256, 256>>>(bias + l * DIM, l, NT, N,
                                               gw, gb, (l == 2) ? 1 : 0);
    }

    k_final<<<1, 128>>>(fc1w, fc1b, fc2w, fc2b, (float*)d_out);
}

// round 16
// speedup vs baseline: 1.2129x; 1.0847x over previous
#include <cuda_runtime.h>
#include <cuda_bf16.h>

#define NMAX 50000
#define EMAX 600000
#define NT2 (2 * NMAX)
#define ET2 (2 * EMAX)
#define DIM 128
#define HEADS 4
#define FH 32
#define NEG_SLOPE 0.2f

// ---------------- scratch (static device globals; no allocs) ----------------
__device__ float d_x[NT2 * DIM];
__device__ __nv_bfloat16 d_hb[NT2 * DIM];
__device__ float d_asrc[NT2 * HEADS];
__device__ float d_adst[NT2 * HEADS];
__device__ float d_gvec[2 * DIM];
__device__ float d_gsum[2];
__device__ float d_gmax[24];                  // [layer][graph][head]
__device__ uint2 d_wpack2[3 * 16 * 16 * 32];  // hi-only tf32 W fragments
__device__ int d_deg[NT2];
__device__ int d_off[NT2 + 1];
__device__ int d_cur[NT2];
__device__ int d_csrc[ET2];
__device__ int d_bsum[128];

__device__ __forceinline__ float leaky(float x) { return x > 0.f ? x : NEG_SLOPE * x; }

__device__ __forceinline__ unsigned f2tf32(float x) {
    unsigned r;
    asm("cvt.rna.tf32.f32 %0, %1;" : "=r"(r) : "f"(x));
    return r;
}

__device__ __forceinline__ float2 bf2f(unsigned w) {
    return __bfloat1622float2(*(__nv_bfloat162*)&w);
}

__device__ __forceinline__ void mma_tf32(float* d, const unsigned* a, unsigned b0, unsigned b1) {
    asm volatile("mma.sync.aligned.m16n8k8.row.col.f32.tf32.tf32.f32 "
                 "{%0,%1,%2,%3}, {%4,%5,%6,%7}, {%8,%9}, {%0,%1,%2,%3};\n"
                 : "+f"(d[0]), "+f"(d[1]), "+f"(d[2]), "+f"(d[3])
                 : "r"(a[0]), "r"(a[1]), "r"(a[2]), "r"(a[3]), "r"(b0), "r"(b1));
}

__device__ __forceinline__ void atomicMaxF(float* addr, float v) {
    int old = __float_as_int(*addr);
    while (__int_as_float(old) < v) {
        int assumed = old;
        old = atomicCAS((int*)addr, assumed, __float_as_int(v));
        if (old == assumed) break;
    }
}

// -------- zero scratch + W pre-pack (hi-only tf32, fragment order) --------
__global__ void k_prep(const float* __restrict__ W, int nt) {
    int i = blockIdx.x * blockDim.x + threadIdx.x;
    if (i < nt) d_deg[i] = 0;
    if (i < 24) d_gmax[i] = -1e30f;
    if (i < 2 * DIM) d_gvec[i] = 0.f;
    if (i < 2) d_gsum[i] = 0.f;
    if (i < 3 * 16 * 16 * 32) {
        int lane = i & 31;
        int n8g = (i >> 5) & 15;
        int kg = (i >> 9) & 15;
        int l = i >> 13;
        int lr = lane >> 2, lq = lane & 3;
        int k0 = kg * 8 + lq, k1 = kg * 8 + lq + 4;
        int nn = n8g * 8 + lr;
        const float* Wl = W + l * DIM * DIM;
        d_wpack2[i] = make_uint2(f2tf32(Wl[k0 * DIM + nn]), f2tf32(Wl[k1 * DIM + nn]));
    }
}

// ---------------- CSR build ----------------
__global__ void k_hist2(const int* __restrict__ ei1, const int* __restrict__ ei2,
                        int E, int n) {
    int i = blockIdx.x * blockDim.x + threadIdx.x;
    if (i < E) atomicAdd(&d_deg[ei1[E + i]], 1);
    else if (i < 2 * E) atomicAdd(&d_deg[ei2[i] + n], 1);
}

__global__ void k_blocksum(int nt) {
    __shared__ int ws[8];
    int base = blockIdx.x * 2048 + threadIdx.x * 8;
    int s = 0;
    #pragma unroll
    for (int k = 0; k < 8; k++) {
        int i = base + k;
        if (i < nt) s += d_deg[i];
    }
    #pragma unroll
    for (int d = 16; d; d >>= 1) s += __shfl_down_sync(0xFFFFFFFFu, s, d);
    if ((threadIdx.x & 31) == 0) ws[threadIdx.x >> 5] = s;
    __syncthreads();
    if (threadIdx.x == 0) {
        int t = 0;
        #pragma unroll
        for (int w = 0; w < 8; w++) t += ws[w];
        d_bsum[blockIdx.x] = t;
    }
}

__global__ void k_scanlocal(int nt) {
    __shared__ int wtot[8];
    __shared__ int wexc[8];
    __shared__ int s_pref;
    int tid = threadIdx.x, lane = tid & 31, wid = tid >> 5;
    if (tid < 32) {
        int a = 0;
        for (int i = tid; i < blockIdx.x; i += 32) a += d_bsum[i];
        #pragma unroll
        for (int d = 16; d; d >>= 1) a += __shfl_down_sync(0xFFFFFFFFu, a, d);
        if (tid == 0) s_pref = a;
    }
    int base = blockIdx.x * 2048 + tid * 8;
    int vals[8];
    int tsum = 0;
    #pragma unroll
    for (int k = 0; k < 8; k++) {
        int i = base + k;
        vals[k] = (i < nt) ? d_deg[i] : 0;
        tsum += vals[k];
    }
    int x = tsum;
    #pragma unroll
    for (int d = 1; d < 32; d <<= 1) {
        int y = __shfl_up_sync(0xFFFFFFFFu, x, d);
        if (lane >= d) x += y;
    }
    if (lane == 31) wtot[wid] = x;
    __syncthreads();
    if (tid == 0) {
        int acc = 0;
        #pragma unroll
        for (int w = 0; w < 8; w++) { wexc[w] = acc; acc += wtot[w]; }
    }
    __syncthreads();
    int running = s_pref + wexc[wid] + (x - tsum);
    #pragma unroll
    for (int k = 0; k < 8; k++) {
        int i = base + k;
        if (i < nt) {
            d_off[i] = running;
            d_cur[i] = running;
            running += vals[k];
            if (i == nt - 1) d_off[nt] = running;
        }
    }
}

__global__ void k_scatter2(const int* __restrict__ ei1, const int* __restrict__ ei2,
                           int E, int n) {
    int i = blockIdx.x * blockDim.x + threadIdx.x;
    if (i < E) {
        int p = atomicAdd(&d_cur[ei1[E + i]], 1);
        d_csrc[p] = ei1[i];
    } else if (i < 2 * E) {
        int j = i - E;
        int p = atomicAdd(&d_cur[ei2[E + j] + n], 1);
        d_csrc[p] = ei2[j] + n;
    }
}

// ------- GEMM (per graph): single-tf32, hi-only packed W, nodes [base, base+cnt) -------
__global__ __launch_bounds__(256) void k_gemm(const float* __restrict__ att_s,
                                              const float* __restrict__ att_d,
                                              int layer, int graph, int base, int cnt,
                                              const int* __restrict__ ids,
                                              const float* __restrict__ embed) {
    __shared__ unsigned xs[64][132];
    int tid = threadIdx.x, warp = tid >> 5, lane = tid & 31;
    int lr = lane >> 2, lq = lane & 3;
    int n0 = base + blockIdx.x * 64;
    int nend = base + cnt;

    for (int t = tid; t < 64 * 32; t += 256) {
        int r = t >> 5, c4 = t & 31;
        int node = n0 + r;
        float4 v = make_float4(0.f, 0.f, 0.f, 0.f);
        if (node < nend) {
            const float* row = (layer == 0)
                ? embed + (size_t)ids[node - base] * DIM
                : d_x + (size_t)node * DIM;
            v = ((const float4*)row)[c4];
        }
        uint4 u = make_uint4(f2tf32(v.x), f2tf32(v.y), f2tf32(v.z), f2tf32(v.w));
        *(uint4*)&xs[r][c4 * 4] = u;
    }
    __syncthreads();

    int wm = warp & 1, wn = warp >> 1;          // wn = head = 32-col quarter
    const uint2* wp = d_wpack2 + layer * 8192 + (wn * 4) * 32 + lane;
    float acc[2][4][4];
    #pragma unroll
    for (int a = 0; a < 2; a++)
        #pragma unroll
        for (int b = 0; b < 4; b++)
            #pragma unroll
            for (int c = 0; c < 4; c++) acc[a][b][c] = 0.f;

    #pragma unroll 4
    for (int k = 0; k < 16; k++) {
        int kb = k * 8;
        unsigned ahi[2][4];
        #pragma unroll
        for (int mt = 0; mt < 2; mt++) {
            int rb = wm * 32 + mt * 16;
            ahi[mt][0] = xs[rb + lr][kb + lq];
            ahi[mt][1] = xs[rb + lr + 8][kb + lq];
            ahi[mt][2] = xs[rb + lr][kb + lq + 4];
            ahi[mt][3] = xs[rb + lr + 8][kb + lq + 4];
        }
        const uint2* wk = wp + k * 512;
        #pragma unroll
        for (int n8 = 0; n8 < 4; n8++) {
            uint2 b = __ldg(&wk[n8 * 32]);
            #pragma unroll
            for (int mt = 0; mt < 2; mt++) {
                mma_tf32(acc[mt][n8], ahi[mt], b.x, b.y);
            }
        }
    }

    float hs[4], hd[4];
    #pragma unroll
    for (int i = 0; i < 4; i++) { hs[i] = 0.f; hd[i] = 0.f; }

    #pragma unroll
    for (int n8 = 0; n8 < 4; n8++) {
        int nb = wn * 32 + n8 * 8 + 2 * lq;
        float2 s2 = *(const float2*)&att_s[nb];
        float2 dd2 = *(const float2*)&att_d[nb];
        #pragma unroll
        for (int mt = 0; mt < 2; mt++) {
            #pragma unroll
            for (int rh = 0; rh < 2; rh++) {
                float c0 = acc[mt][n8][rh * 2], c1 = acc[mt][n8][rh * 2 + 1];
                int node = n0 + wm * 32 + mt * 16 + rh * 8 + lr;
                if (node < nend)
                    *(__nv_bfloat162*)&d_hb[(size_t)node * DIM + nb] =
                        __floats2bfloat162_rn(c0, c1);
                int ri = mt * 2 + rh;
                hs[ri] += c0 * s2.x + c1 * s2.y;
                hd[ri] += c0 * dd2.x + c1 * dd2.y;
            }
        }
    }

    float wmax = -1e30f;
    #pragma unroll
    for (int ri = 0; ri < 4; ri++) {
        float vs = hs[ri], vd = hd[ri];
        vs += __shfl_xor_sync(0xFFFFFFFFu, vs, 1);
        vs += __shfl_xor_sync(0xFFFFFFFFu, vs, 2);
        vd += __shfl_xor_sync(0xFFFFFFFFu, vd, 1);
        vd += __shfl_xor_sync(0xFFFFFFFFu, vd, 2);
        int mt = ri >> 1, rh = ri & 1;
        int node = n0 + wm * 32 + mt * 16 + rh * 8 + lr;
        if (lq == 0 && node < nend) {
            d_asrc[node * HEADS + wn] = vs;
            d_adst[node * HEADS + wn] = vd;
        }
        wmax = fmaxf(wmax, vs);
    }
    #pragma unroll
    for (int d = 16; d; d >>= 1) wmax = fmaxf(wmax, __shfl_xor_sync(0xFFFFFFFFu, wmax, d));
    if (lane == 0) atomicMaxF(&d_gmax[layer * 8 + graph * 4 + wn], wmax);
}

// ------ attention (per graph): single-pass, half-warp edge parallel ------
__global__ __launch_bounds__(256) void k_attn(const float* __restrict__ bias,
                                              int layer, int graph, int base, int cnt,
                                              const float* __restrict__ gw,
                                              const float* __restrict__ gb,
                                              int last) {
    __shared__ float sgv[DIM];
    __shared__ float sgs;
    int tid = threadIdx.x;
    if (last) {
        if (tid < DIM) sgv[tid] = 0.f;
        if (tid == 0) sgs = 0.f;
        __syncthreads();
    }
    int warp = (blockIdx.x * 256 + tid) >> 5;
    int lane = tid & 31;
    int hw = lane >> 4;
    int sl = lane & 15;
    int h3 = sl >> 2;
    int fb = sl * 8 + hw * 4;
    bool active = warp < cnt;
    int nidx = base + warp;
    float4 ra = make_float4(0.f, 0.f, 0.f, 0.f);

    if (active) {
        int beg = d_off[nidx], end = d_off[nidx + 1];
        float ad_h = __ldg(&d_adst[nidx * HEADS + h3]);
        float m_h = leaky(__ldg(&d_gmax[layer * 8 + graph * 4 + h3]) + ad_h);
        float as_h = __ldg(&d_asrc[nidx * HEADS + h3]);
        float exself = __expf(leaky(as_h + ad_h) - m_h);
        float eself = hw ? 0.f : exself;

        uint4 sr = ((const uint4*)(d_hb + (size_t)nidx * DIM))[sl];
        float2 f0 = bf2f(sr.x), f1 = bf2f(sr.y), f2 = bf2f(sr.z), f3 = bf2f(sr.w);
        float4 accA = make_float4(eself * f0.x, eself * f0.y, eself * f1.x, eself * f1.y);
        float4 accB = make_float4(eself * f2.x, eself * f2.y, eself * f3.x, eself * f3.y);
        float sum = eself;

        for (int p = beg; p < end; p += 2) {
            int idx = p + hw;
            float valid = (idx < end) ? 1.f : 0.f;
            int s = d_csrc[min(idx, end - 1)];
            float a = __ldg(&d_asrc[s * HEADS + h3]);
            float e = valid * __expf(leaky(a + ad_h) - m_h);
            sum += e;
            uint4 r = ((const uint4*)(d_hb + (size_t)s * DIM))[sl];
            float2 g0 = bf2f(r.x), g1 = bf2f(r.y), g2 = bf2f(r.z), g3 = bf2f(r.w);
            accA.x += e * g0.x; accA.y += e * g0.y; accA.z += e * g1.x; accA.w += e * g1.y;
            accB.x += e * g2.x; accB.y += e * g2.y; accB.z += e * g3.x; accB.w += e * g3.y;
        }

        sum += __shfl_xor_sync(0xFFFFFFFFu, sum, 16);
        accA.x += __shfl_xor_sync(0xFFFFFFFFu, accA.x, 16);
        accA.y += __shfl_xor_sync(0xFFFFFFFFu, accA.y, 16);
        accA.z += __shfl_xor_sync(0xFFFFFFFFu, accA.z, 16);
        accA.w += __shfl_xor_sync(0xFFFFFFFFu, accA.w, 16);
        accB.x += __shfl_xor_sync(0xFFFFFFFFu, accB.x, 16);
        accB.y += __shfl_xor_sync(0xFFFFFFFFu, accB.y, 16);
        accB.z += __shfl_xor_sync(0xFFFFFFFFu, accB.z, 16);
        accB.w += __shfl_xor_sync(0xFFFFFFFFu, accB.w, 16);

        float inv = 1.f / sum;
        float4 acc = hw ? accB : accA;
        float4 b = *(const float4*)&bias[fb];
        ra.x = fmaxf(acc.x * inv + b.x, 0.f);
        ra.y = fmaxf(acc.y * inv + b.y, 0.f);
        ra.z = fmaxf(acc.z * inv + b.z, 0.f);
        ra.w = fmaxf(acc.w * inv + b.w, 0.f);
    }

    if (!last) {
        if (active)
            *(float4*)&d_x[(size_t)nidx * DIM + fb] = ra;
        return;
    }

    // last layer: fused global-attention pooling for this graph
    if (active) {
        float4 wv = *(const float4*)&gw[fb];
        float t = ra.x * wv.x + ra.y * wv.y + ra.z * wv.z + ra.w * wv.w;
        #pragma unroll
        for (int d = 16; d; d >>= 1) t += __shfl_xor_sync(0xFFFFFFFFu, t, d);
        float sg = 1.f / (1.f + __expf(-(t + gb[0])));
        float gate = __expf(sg);
        float* bp = sgv + fb;
        atomicAdd(bp + 0, gate * ra.x);
        atomicAdd(bp + 1, gate * ra.y);
        atomicAdd(bp + 2, gate * ra.z);
        atomicAdd(bp + 3, gate * ra.w);
        if (lane == 0) atomicAdd(&sgs, gate);
    }
    __syncthreads();
    if (tid == 0 && sgs != 0.f) atomicAdd(&d_gsum[graph], sgs);
    if (tid < DIM) {
        float v = sgv[tid];
        if (v != 0.f) atomicAdd(&d_gvec[graph * DIM + tid], v);
    }
}

// ---------------- final MLP ----------------
__global__ void k_final(const float* __restrict__ fc1_w, const float* __restrict__ fc1_b,
                        const float* __restrict__ fc2_w, const float* __restrict__ fc2_b,
                        float* __restrict__ out) {
    __shared__ float red[4];
    int j = threadIdx.x;
    float inv1 = 1.f / d_gsum[0];
    float inv2 = 1.f / d_gsum[1];
    float acc = fc1_b[j];
    #pragma unroll 4
    for (int k = 0; k < DIM; k++)
        acc += d_gvec[k] * inv1 * fc1_w[k * DIM + j];
    #pragma unroll 4
    for (int k = 0; k < DIM; k++)
        acc += d_gvec[DIM + k] * inv2 * fc1_w[(DIM + k) * DIM + j];
    float v = fmaxf(acc, 0.f) * fc2_w[j];
    #pragma unroll
    for (int d = 16; d; d >>= 1) v += __shfl_down_sync(0xFFFFFFFFu, v, d);
    if ((j & 31) == 0) red[j >> 5] = v;
    __syncthreads();
    if (j == 0) out[0] = red[0] + red[1] + red[2] + red[3] + fc2_b[0];
}

// ---------------- orchestration: two graph pipelines on two streams ----------------
static cudaStream_t g_s2 = nullptr;   // CSR build
static cudaStream_t g_s3 = nullptr;   // graph-B pipeline
static cudaEvent_t g_evPrep = nullptr, g_evCSR = nullptr, g_evB = nullptr;

extern "C" void kernel_launch(void* const* d_in, const int* in_sizes, int n_in,
                              void* d_out, int out_size) {
    (void)n_in; (void)out_size;
    const int*   x1    = (const int*)d_in[0];
    const int*   x2    = (const int*)d_in[1];
    const int*   ei1   = (const int*)d_in[2];
    const int*   ei2   = (const int*)d_in[3];
    const float* embed = (const float*)d_in[4];
    const float* W     = (const float*)d_in[5];
    const float* att_s = (const float*)d_in[6];
    const float* att_d = (const float*)d_in[7];
    const float* bias  = (const float*)d_in[8];
    const float* gw    = (const float*)d_in[9];
    const float* gb    = (const float*)d_in[10];
    const float* fc1w  = (const float*)d_in[11];
    const float* fc1b  = (const float*)d_in[12];
    const float* fc2w  = (const float*)d_in[13];
    const float* fc2b  = (const float*)d_in[14];

    int N = in_sizes[0];
    int E = in_sizes[2] / 2;
    int NT = 2 * N;
    int nb = (NT + 2047) / 2048;
    int gemm_grid = (N + 63) / 64;
    int attn_grid = (N * 32 + 255) / 256;

    if (!g_s2) {
        cudaStreamCreateWithFlags(&g_s2, cudaStreamNonBlocking);
        cudaStreamCreateWithFlags(&g_s3, cudaStreamNonBlocking);
        cudaEventCreateWithFlags(&g_evPrep, cudaEventDisableTiming);
        cudaEventCreateWithFlags(&g_evCSR, cudaEventDisableTiming);
        cudaEventCreateWithFlags(&g_evB, cudaEventDisableTiming);
    }

    // prep (main)
    k_prep<<<(NT + 255) / 256, 256>>>(W, NT);
    cudaEventRecord(g_evPrep, 0);

    // CSR build on s2 (needs d_deg zeroed)
    cudaStreamWaitEvent(g_s2, g_evPrep, 0);
    k_hist2<<<(2 * E + 255) / 256, 256, 0, g_s2>>>(ei1, ei2, E, N);
    k_blocksum<<<nb, 256, 0, g_s2>>>(NT);

    // graph-A layer-0 GEMM (main; 4th submitted launch -> ncu profiles this)
    k_gemm<<<gemm_grid, 256>>>(att_s, att_d, 0, 0, 0, N, x1, embed);

    k_scanlocal<<<nb, 256, 0, g_s2>>>(NT);
    k_scatter2<<<(2 * E + 255) / 256, 256, 0, g_s2>>>(ei1, ei2, E, N);
    cudaEventRecord(g_evCSR, g_s2);

    // graph-B layer-0 GEMM (s3; needs prep only)
    cudaStreamWaitEvent(g_s3, g_evPrep, 0);
    k_gemm<<<gemm_grid, 256, 0, g_s3>>>(att_s, att_d, 0, 1, N, N, x2, embed);

    // graph-A pipeline (main)
    cudaStreamWaitEvent(0, g_evCSR, 0);
    k_attn<<<attn_grid, 256>>>(bias, 0, 0, 0, N, gw, gb, 0);
    for (int l = 1; l < 3; l++) {
        k_gemm<<<gemm_grid, 256>>>(att_s + l * HEADS * FH, att_d + l * HEADS * FH,
                                   l, 0, 0, N, x1, embed);
        k_attn<<<attn_grid, 256>>>(bias + l * DIM, l, 0, 0, N, gw, gb, (l == 2) ? 1 : 0);
    }

    // graph-B pipeline (s3)
    cudaStreamWaitEvent(g_s3, g_evCSR, 0);
    k_attn<<<attn_grid, 256, 0, g_s3>>>(bias, 0, 1, N, N, gw, gb, 0);
    for (int l = 1; l < 3; l++) {
        k_gemm<<<gemm_grid, 256, 0, g_s3>>>(att_s + l * HEADS * FH, att_d + l * HEADS * FH,
                                            l, 1, N, N, x2, embed);
        k_attn<<<attn_grid, 256, 0, g_s3>>>(bias + l * DIM, l, 1, N, N, gw, gb,
                                            (l == 2) ? 1 : 0);
    }
    cudaEventRecord(g_evB, g_s3);

    // join + final MLP
    cudaStreamWaitEvent(0, g_evB, 0);
    k_final<<<1, 128>>>(fc1w, fc1b, fc2w, fc2b, (float*)d_out);
}

// round 17
// speedup vs baseline: 1.2904x; 1.0639x over previous
#include <cuda_runtime.h>
#include <cuda_bf16.h>

#define NMAX 50000
#define EMAX 600000
#define NT2 (2 * NMAX)
#define ET2 (2 * EMAX)
#define DIM 128
#define HEADS 4
#define FH 32
#define NEG_SLOPE 0.2f

// ---------------- scratch (static device globals; no allocs) ----------------
__device__ float d_x[NT2 * DIM];
__device__ __nv_bfloat16 d_hb[NT2 * DIM];
__device__ float d_asrc[NT2 * HEADS];
__device__ float d_adst[NT2 * HEADS];
__device__ float d_gvec[2 * DIM];
__device__ float d_gsum[2];
__device__ float d_gmax[24];                   // [layer][graph][head]
__device__ uint2 d_wpackh[3 * 8 * 16 * 32];    // bf16 W fragments (m16n8k16)
__device__ int d_deg[NT2];
__device__ int d_off[NT2 + 1];
__device__ int d_cur[NT2];
__device__ int d_csrc[ET2];
__device__ int d_bsum[128];

__device__ __forceinline__ float leaky(float x) { return x > 0.f ? x : NEG_SLOPE * x; }

__device__ __forceinline__ unsigned bfpack(float a, float b) {
    __nv_bfloat162 p = __floats2bfloat162_rn(a, b);
    return *(unsigned*)&p;
}

__device__ __forceinline__ float2 bf2f(unsigned w) {
    return __bfloat1622float2(*(__nv_bfloat162*)&w);
}

__device__ __forceinline__ void mma_bf16(float* d, const unsigned* a, unsigned b0, unsigned b1) {
    asm volatile("mma.sync.aligned.m16n8k16.row.col.f32.bf16.bf16.f32 "
                 "{%0,%1,%2,%3}, {%4,%5,%6,%7}, {%8,%9}, {%0,%1,%2,%3};\n"
                 : "+f"(d[0]), "+f"(d[1]), "+f"(d[2]), "+f"(d[3])
                 : "r"(a[0]), "r"(a[1]), "r"(a[2]), "r"(a[3]), "r"(b0), "r"(b1));
}

__device__ __forceinline__ void atomicMaxF(float* addr, float v) {
    int old = __float_as_int(*addr);
    while (__int_as_float(old) < v) {
        int assumed = old;
        old = atomicCAS((int*)addr, assumed, __float_as_int(v));
        if (old == assumed) break;
    }
}

// -------- zero scratch + W pre-pack (bf16, m16n8k16 fragment order) --------
__global__ void k_prep(const float* __restrict__ W, int nt) {
    int i = blockIdx.x * blockDim.x + threadIdx.x;
    if (i < nt) d_deg[i] = 0;
    if (i < 24) d_gmax[i] = -1e30f;
    if (i < 2 * DIM) d_gvec[i] = 0.f;
    if (i < 2) d_gsum[i] = 0.f;
    if (i < 3 * 8 * 16 * 32) {
        int lane = i & 31;
        int n8g = (i >> 5) & 15;
        int kg = (i >> 9) & 7;
        int l = i >> 12;
        int lr = lane >> 2, lq = lane & 3;
        int k0 = kg * 16 + 2 * lq;
        int nn = n8g * 8 + lr;
        const float* Wl = W + l * DIM * DIM;
        unsigned b0 = bfpack(Wl[k0 * DIM + nn], Wl[(k0 + 1) * DIM + nn]);
        unsigned b1 = bfpack(Wl[(k0 + 8) * DIM + nn], Wl[(k0 + 9) * DIM + nn]);
        d_wpackh[i] = make_uint2(b0, b1);
    }
}

// ---------------- CSR build ----------------
__global__ void k_hist2(const int* __restrict__ ei1, const int* __restrict__ ei2,
                        int E, int n) {
    int i = blockIdx.x * blockDim.x + threadIdx.x;
    if (i < E) atomicAdd(&d_deg[ei1[E + i]], 1);
    else if (i < 2 * E) atomicAdd(&d_deg[ei2[i] + n], 1);
}

__global__ void k_blocksum(int nt) {
    __shared__ int ws[8];
    int base = blockIdx.x * 2048 + threadIdx.x * 8;
    int s = 0;
    #pragma unroll
    for (int k = 0; k < 8; k++) {
        int i = base + k;
        if (i < nt) s += d_deg[i];
    }
    #pragma unroll
    for (int d = 16; d; d >>= 1) s += __shfl_down_sync(0xFFFFFFFFu, s, d);
    if ((threadIdx.x & 31) == 0) ws[threadIdx.x >> 5] = s;
    __syncthreads();
    if (threadIdx.x == 0) {
        int t = 0;
        #pragma unroll
        for (int w = 0; w < 8; w++) t += ws[w];
        d_bsum[blockIdx.x] = t;
    }
}

__global__ void k_scanlocal(int nt) {
    __shared__ int wtot[8];
    __shared__ int wexc[8];
    __shared__ int s_pref;
    int tid = threadIdx.x, lane = tid & 31, wid = tid >> 5;
    if (tid < 32) {
        int a = 0;
        for (int i = tid; i < blockIdx.x; i += 32) a += d_bsum[i];
        #pragma unroll
        for (int d = 16; d; d >>= 1) a += __shfl_down_sync(0xFFFFFFFFu, a, d);
        if (tid == 0) s_pref = a;
    }
    int base = blockIdx.x * 2048 + tid * 8;
    int vals[8];
    int tsum = 0;
    #pragma unroll
    for (int k = 0; k < 8; k++) {
        int i = base + k;
        vals[k] = (i < nt) ? d_deg[i] : 0;
        tsum += vals[k];
    }
    int x = tsum;
    #pragma unroll
    for (int d = 1; d < 32; d <<= 1) {
        int y = __shfl_up_sync(0xFFFFFFFFu, x, d);
        if (lane >= d) x += y;
    }
    if (lane == 31) wtot[wid] = x;
    __syncthreads();
    if (tid == 0) {
        int acc = 0;
        #pragma unroll
        for (int w = 0; w < 8; w++) { wexc[w] = acc; acc += wtot[w]; }
    }
    __syncthreads();
    int running = s_pref + wexc[wid] + (x - tsum);
    #pragma unroll
    for (int k = 0; k < 8; k++) {
        int i = base + k;
        if (i < nt) {
            d_off[i] = running;
            d_cur[i] = running;
            running += vals[k];
            if (i == nt - 1) d_off[nt] = running;
        }
    }
}

__global__ void k_scatter2(const int* __restrict__ ei1, const int* __restrict__ ei2,
                           int E, int n) {
    int i = blockIdx.x * blockDim.x + threadIdx.x;
    if (i < E) {
        int p = atomicAdd(&d_cur[ei1[E + i]], 1);
        d_csrc[p] = ei1[i];
    } else if (i < 2 * E) {
        int j = i - E;
        int p = atomicAdd(&d_cur[ei2[E + j] + n], 1);
        d_csrc[p] = ei2[j] + n;
    }
}

// ------- GEMM (per graph): bf16 m16n8k16, packed W, nodes [base, base+cnt) -------
// 64-row tile, 256 threads. A in smem as bf16x2, stride 68 (conflict-free).
// Hot loop per k16: 8 LDS.32 (A) + 4 LDG.64 (W) + 8 MMA.
__global__ __launch_bounds__(256) void k_gemm(const float* __restrict__ att_s,
                                              const float* __restrict__ att_d,
                                              int layer, int graph, int base, int cnt,
                                              const int* __restrict__ ids,
                                              const float* __restrict__ embed) {
    __shared__ unsigned xs[64][68];   // bf16x2: 64 uints/row + pad 4
    int tid = threadIdx.x, warp = tid >> 5, lane = tid & 31;
    int lr = lane >> 2, lq = lane & 3;
    int n0 = base + blockIdx.x * 64;
    int nend = base + cnt;

    for (int t = tid; t < 64 * 32; t += 256) {
        int r = t >> 5, c4 = t & 31;
        int node = n0 + r;
        float4 v = make_float4(0.f, 0.f, 0.f, 0.f);
        if (node < nend) {
            const float* row = (layer == 0)
                ? embed + (size_t)ids[node - base] * DIM
                : d_x + (size_t)node * DIM;
            v = ((const float4*)row)[c4];
        }
        xs[r][c4 * 2] = bfpack(v.x, v.y);
        xs[r][c4 * 2 + 1] = bfpack(v.z, v.w);
    }
    __syncthreads();

    int wm = warp & 1, wn = warp >> 1;          // wn = head = 32-col quarter
    const uint2* wp = d_wpackh + layer * 4096 + (wn * 4) * 32 + lane;
    float acc[2][4][4];
    #pragma unroll
    for (int a = 0; a < 2; a++)
        #pragma unroll
        for (int b = 0; b < 4; b++)
            #pragma unroll
            for (int c = 0; c < 4; c++) acc[a][b][c] = 0.f;

    #pragma unroll 2
    for (int k = 0; k < 8; k++) {
        int kb = k * 8;
        unsigned af[2][4];
        #pragma unroll
        for (int mt = 0; mt < 2; mt++) {
            int rb = wm * 32 + mt * 16;
            af[mt][0] = xs[rb + lr][kb + lq];
            af[mt][1] = xs[rb + lr + 8][kb + lq];
            af[mt][2] = xs[rb + lr][kb + lq + 4];
            af[mt][3] = xs[rb + lr + 8][kb + lq + 4];
        }
        const uint2* wk = wp + k * 512;
        #pragma unroll
        for (int n8 = 0; n8 < 4; n8++) {
            uint2 b = __ldg(&wk[n8 * 32]);
            #pragma unroll
            for (int mt = 0; mt < 2; mt++) {
                mma_bf16(acc[mt][n8], af[mt], b.x, b.y);
            }
        }
    }

    // epilogue: store h (bf16), per-head alpha dots (head = wn), global max
    float hs[4], hd[4];
    #pragma unroll
    for (int i = 0; i < 4; i++) { hs[i] = 0.f; hd[i] = 0.f; }

    #pragma unroll
    for (int n8 = 0; n8 < 4; n8++) {
        int nb = wn * 32 + n8 * 8 + 2 * lq;
        float2 s2 = *(const float2*)&att_s[nb];
        float2 dd2 = *(const float2*)&att_d[nb];
        #pragma unroll
        for (int mt = 0; mt < 2; mt++) {
            #pragma unroll
            for (int rh = 0; rh < 2; rh++) {
                float c0 = acc[mt][n8][rh * 2], c1 = acc[mt][n8][rh * 2 + 1];
                int node = n0 + wm * 32 + mt * 16 + rh * 8 + lr;
                if (node < nend)
                    *(__nv_bfloat162*)&d_hb[(size_t)node * DIM + nb] =
                        __floats2bfloat162_rn(c0, c1);
                int ri = mt * 2 + rh;
                hs[ri] += c0 * s2.x + c1 * s2.y;
                hd[ri] += c0 * dd2.x + c1 * dd2.y;
            }
        }
    }

    float wmax = -1e30f;
    #pragma unroll
    for (int ri = 0; ri < 4; ri++) {
        float vs = hs[ri], vd = hd[ri];
        vs += __shfl_xor_sync(0xFFFFFFFFu, vs, 1);
        vs += __shfl_xor_sync(0xFFFFFFFFu, vs, 2);
        vd += __shfl_xor_sync(0xFFFFFFFFu, vd, 1);
        vd += __shfl_xor_sync(0xFFFFFFFFu, vd, 2);
        int mt = ri >> 1, rh = ri & 1;
        int node = n0 + wm * 32 + mt * 16 + rh * 8 + lr;
        if (lq == 0 && node < nend) {
            d_asrc[node * HEADS + wn] = vs;
            d_adst[node * HEADS + wn] = vd;
        }
        wmax = fmaxf(wmax, vs);
    }
    #pragma unroll
    for (int d = 16; d; d >>= 1) wmax = fmaxf(wmax, __shfl_xor_sync(0xFFFFFFFFu, wmax, d));
    if (lane == 0) atomicMaxF(&d_gmax[layer * 8 + graph * 4 + wn], wmax);
}

// ------ attention (per graph): single-pass, half-warp edge parallel ------
__global__ __launch_bounds__(256) void k_attn(const float* __restrict__ bias,
                                              int layer, int graph, int base, int cnt,
                                              const float* __restrict__ gw,
                                              const float* __restrict__ gb,
                                              int last) {
    __shared__ float sgv[DIM];
    __shared__ float sgs;
    int tid = threadIdx.x;
    if (last) {
        if (tid < DIM) sgv[tid] = 0.f;
        if (tid == 0) sgs = 0.f;
        __syncthreads();
    }
    int warp = (blockIdx.x * 256 + tid) >> 5;
    int lane = tid & 31;
    int hw = lane >> 4;
    int sl = lane & 15;
    int h3 = sl >> 2;
    int fb = sl * 8 + hw * 4;
    bool active = warp < cnt;
    int nidx = base + warp;
    float4 ra = make_float4(0.f, 0.f, 0.f, 0.f);

    if (active) {
        int beg = d_off[nidx], end = d_off[nidx + 1];
        float ad_h = __ldg(&d_adst[nidx * HEADS + h3]);
        float m_h = leaky(__ldg(&d_gmax[layer * 8 + graph * 4 + h3]) + ad_h);
        float as_h = __ldg(&d_asrc[nidx * HEADS + h3]);
        float exself = __expf(leaky(as_h + ad_h) - m_h);
        float eself = hw ? 0.f : exself;

        uint4 sr = ((const uint4*)(d_hb + (size_t)nidx * DIM))[sl];
        float2 f0 = bf2f(sr.x), f1 = bf2f(sr.y), f2 = bf2f(sr.z), f3 = bf2f(sr.w);
        float4 accA = make_float4(eself * f0.x, eself * f0.y, eself * f1.x, eself * f1.y);
        float4 accB = make_float4(eself * f2.x, eself * f2.y, eself * f3.x, eself * f3.y);
        float sum = eself;

        for (int p = beg; p < end; p += 2) {
            int idx = p + hw;
            float valid = (idx < end) ? 1.f : 0.f;
            int s = d_csrc[min(idx, end - 1)];
            float a = __ldg(&d_asrc[s * HEADS + h3]);
            float e = valid * __expf(leaky(a + ad_h) - m_h);
            sum += e;
            uint4 r = ((const uint4*)(d_hb + (size_t)s * DIM))[sl];
            float2 g0 = bf2f(r.x), g1 = bf2f(r.y), g2 = bf2f(r.z), g3 = bf2f(r.w);
            accA.x += e * g0.x; accA.y += e * g0.y; accA.z += e * g1.x; accA.w += e * g1.y;
            accB.x += e * g2.x; accB.y += e * g2.y; accB.z += e * g3.x; accB.w += e * g3.y;
        }

        sum += __shfl_xor_sync(0xFFFFFFFFu, sum, 16);
        accA.x += __shfl_xor_sync(0xFFFFFFFFu, accA.x, 16);
        accA.y += __shfl_xor_sync(0xFFFFFFFFu, accA.y, 16);
        accA.z += __shfl_xor_sync(0xFFFFFFFFu, accA.z, 16);
        accA.w += __shfl_xor_sync(0xFFFFFFFFu, accA.w, 16);
        accB.x += __shfl_xor_sync(0xFFFFFFFFu, accB.x, 16);
        accB.y += __shfl_xor_sync(0xFFFFFFFFu, accB.y, 16);
        accB.z += __shfl_xor_sync(0xFFFFFFFFu, accB.z, 16);
        accB.w += __shfl_xor_sync(0xFFFFFFFFu, accB.w, 16);

        float inv = 1.f / sum;
        float4 acc = hw ? accB : accA;
        float4 b = *(const float4*)&bias[fb];
        ra.x = fmaxf(acc.x * inv + b.x, 0.f);
        ra.y = fmaxf(acc.y * inv + b.y, 0.f);
        ra.z = fmaxf(acc.z * inv + b.z, 0.f);
        ra.w = fmaxf(acc.w * inv + b.w, 0.f);
    }

    if (!last) {
        if (active)
            *(float4*)&d_x[(size_t)nidx * DIM + fb] = ra;
        return;
    }

    if (active) {
        float4 wv = *(const float4*)&gw[fb];
        float t = ra.x * wv.x + ra.y * wv.y + ra.z * wv.z + ra.w * wv.w;
        #pragma unroll
        for (int d = 16; d; d >>= 1) t += __shfl_xor_sync(0xFFFFFFFFu, t, d);
        float sg = 1.f / (1.f + __expf(-(t + gb[0])));
        float gate = __expf(sg);
        float* bp = sgv + fb;
        atomicAdd(bp + 0, gate * ra.x);
        atomicAdd(bp + 1, gate * ra.y);
        atomicAdd(bp + 2, gate * ra.z);
        atomicAdd(bp + 3, gate * ra.w);
        if (lane == 0) atomicAdd(&sgs, gate);
    }
    __syncthreads();
    if (tid == 0 && sgs != 0.f) atomicAdd(&d_gsum[graph], sgs);
    if (tid < DIM) {
        float v = sgv[tid];
        if (v != 0.f) atomicAdd(&d_gvec[graph * DIM + tid], v);
    }
}

// ---------------- final MLP ----------------
__global__ void k_final(const float* __restrict__ fc1_w, const float* __restrict__ fc1_b,
                        const float* __restrict__ fc2_w, const float* __restrict__ fc2_b,
                        float* __restrict__ out) {
    __shared__ float red[4];
    int j = threadIdx.x;
    float inv1 = 1.f / d_gsum[0];
    float inv2 = 1.f / d_gsum[1];
    float acc = fc1_b[j];
    #pragma unroll 4
    for (int k = 0; k < DIM; k++)
        acc += d_gvec[k] * inv1 * fc1_w[k * DIM + j];
    #pragma unroll 4
    for (int k = 0; k < DIM; k++)
        acc += d_gvec[DIM + k] * inv2 * fc1_w[(DIM + k) * DIM + j];
    float v = fmaxf(acc, 0.f) * fc2_w[j];
    #pragma unroll
    for (int d = 16; d; d >>= 1) v += __shfl_down_sync(0xFFFFFFFFu, v, d);
    if ((j & 31) == 0) red[j >> 5] = v;
    __syncthreads();
    if (j == 0) out[0] = red[0] + red[1] + red[2] + red[3] + fc2_b[0];
}

// ---------------- orchestration: two graph pipelines on two streams ----------------
static cudaStream_t g_s2 = nullptr;   // CSR build
static cudaStream_t g_s3 = nullptr;   // graph-B pipeline
static cudaEvent_t g_evPrep = nullptr, g_evCSR = nullptr, g_evB = nullptr;

extern "C" void kernel_launch(void* const* d_in, const int* in_sizes, int n_in,
                              void* d_out, int out_size) {
    (void)n_in; (void)out_size;
    const int*   x1    = (const int*)d_in[0];
    const int*   x2    = (const int*)d_in[1];
    const int*   ei1   = (const int*)d_in[2];
    const int*   ei2   = (const int*)d_in[3];
    const float* embed = (const float*)d_in[4];
    const float* W     = (const float*)d_in[5];
    const float* att_s = (const float*)d_in[6];
    const float* att_d = (const float*)d_in[7];
    const float* bias  = (const float*)d_in[8];
    const float* gw    = (const float*)d_in[9];
    const float* gb    = (const float*)d_in[10];
    const float* fc1w  = (const float*)d_in[11];
    const float* fc1b  = (const float*)d_in[12];
    const float* fc2w  = (const float*)d_in[13];
    const float* fc2b  = (const float*)d_in[14];

    int N = in_sizes[0];
    int E = in_sizes[2] / 2;
    int NT = 2 * N;
    int nb = (NT + 2047) / 2048;
    int gemm_grid = (N + 63) / 64;
    int attn_grid = (N * 32 + 255) / 256;

    if (!g_s2) {
        cudaStreamCreateWithFlags(&g_s2, cudaStreamNonBlocking);
        cudaStreamCreateWithFlags(&g_s3, cudaStreamNonBlocking);
        cudaEventCreateWithFlags(&g_evPrep, cudaEventDisableTiming);
        cudaEventCreateWithFlags(&g_evCSR, cudaEventDisableTiming);
        cudaEventCreateWithFlags(&g_evB, cudaEventDisableTiming);
    }

    // prep (main)
    k_prep<<<(NT + 255) / 256, 256>>>(W, NT);
    cudaEventRecord(g_evPrep, 0);

    // CSR build on s2 (needs d_deg zeroed)
    cudaStreamWaitEvent(g_s2, g_evPrep, 0);
    k_hist2<<<(2 * E + 255) / 256, 256, 0, g_s2>>>(ei1, ei2, E, N);
    k_blocksum<<<nb, 256, 0, g_s2>>>(NT);

    // graph-A layer-0 GEMM (main; 4th submitted launch -> ncu profiles this)
    k_gemm<<<gemm_grid, 256>>>(att_s, att_d, 0, 0, 0, N, x1, embed);

    k_scanlocal<<<nb, 256, 0, g_s2>>>(NT);
    k_scatter2<<<(2 * E + 255) / 256, 256, 0, g_s2>>>(ei1, ei2, E, N);
    cudaEventRecord(g_evCSR, g_s2);

    // graph-B layer-0 GEMM (s3; needs prep only)
    cudaStreamWaitEvent(g_s3, g_evPrep, 0);
    k_gemm<<<gemm_grid, 256, 0, g_s3>>>(att_s, att_d, 0, 1, N, N, x2, embed);

    // graph-A pipeline (main)
    cudaStreamWaitEvent(0, g_evCSR, 0);
    k_attn<<<attn_grid, 256>>>(bias, 0, 0, 0, N, gw, gb, 0);
    for (int l = 1; l < 3; l++) {
        k_gemm<<<gemm_grid, 256>>>(att_s + l * HEADS * FH, att_d + l * HEADS * FH,
                                   l, 0, 0, N, x1, embed);
        k_attn<<<attn_grid, 256>>>(bias + l * DIM, l, 0, 0, N, gw, gb, (l == 2) ? 1 : 0);
    }

    // graph-B pipeline (s3)
    cudaStreamWaitEvent(g_s3, g_evCSR, 0);
    k_attn<<<attn_grid, 256, 0, g_s3>>>(bias, 0, 1, N, N, gw, gb, 0);
    for (int l = 1; l < 3; l++) {
        k_gemm<<<gemm_grid, 256, 0, g_s3>>>(att_s + l * HEADS * FH, att_d + l * HEADS * FH,
                                            l, 1, N, N, x2, embed);
        k_attn<<<attn_grid, 256, 0, g_s3>>>(bias + l * DIM, l, 1, N, N, gw, gb,
                                            (l == 2) ? 1 : 0);
    }
    cudaEventRecord(g_evB, g_s3);

    // join + final MLP
    cudaStreamWaitEvent(0, g_evB, 0);
    k_final<<<1, 128>>>(fc1w, fc1b, fc2w, fc2b, (float*)d_out);
}